// round 7
// baseline (speedup 1.0000x reference)
#include <cuda_runtime.h>
#include <cuda_bf16.h>
#include <cstdint>
#include <math.h>

#define kVocab 50000
#define kEmbed 300
#define kEmbP  320
#define kUnits 512
#define kT 128
#define kB 512
#define kG 2048

// ---------------- global scratch ----------------
__device__ float g_zpre[(size_t)kB * kT * kG];
__device__ unsigned g_bar;
__device__ __align__(128) __nv_bfloat16 g_u_hi[kG * kUnits];     // U^T gate-interleaved [n'][k]
__device__ __align__(128) __nv_bfloat16 g_u_lo[kG * kUnits];
__device__ __align__(128) __nv_bfloat16 g_hb_hi[2][kB * kUnits]; // h bf16, double buffered
__device__ __align__(128) __nv_bfloat16 g_hb_lo[2][kB * kUnits];
__device__ __align__(128) __nv_bfloat16 g_emb_hi[(size_t)kVocab * kEmbP];
__device__ __align__(128) __nv_bfloat16 g_emb_lo[(size_t)kVocab * kEmbP];
__device__ __align__(128) __nv_bfloat16 g_wt_hi[kG * kEmbP];
__device__ __align__(128) __nv_bfloat16 g_wt_lo[kG * kEmbP];

// ---------------- helpers ----------------
__device__ __forceinline__ uint32_t smem_u32(const void* p) {
    uint32_t a;
    asm("{ .reg .u64 t; cvta.to.shared.u64 t, %1; cvt.u32.u64 %0, t; }" : "=r"(a) : "l"(p));
    return a;
}
#define CP_ASYNC16(dst, src) \
    asm volatile("cp.async.ca.shared.global [%0], [%1], 16;" :: "r"(dst), "l"(src) : "memory")
#define CP_COMMIT() asm volatile("cp.async.commit_group;" ::: "memory")
#define CP_WAIT0()  asm volatile("cp.async.wait_group 0;" ::: "memory")
#define CP_WAIT1()  asm volatile("cp.async.wait_group 1;" ::: "memory")

#define LDMATRIX_X4(r0, r1, r2, r3, addr) \
    asm volatile("ldmatrix.sync.aligned.m8n8.x4.shared.b16 {%0,%1,%2,%3}, [%4];" \
        : "=r"(r0), "=r"(r1), "=r"(r2), "=r"(r3) : "r"(addr))

#define MMA_BF16(c0, c1, c2, c3, a0, a1, a2, a3, b0, b1) \
    asm volatile("mma.sync.aligned.m16n8k16.row.col.f32.bf16.bf16.f32 " \
        "{%0,%1,%2,%3}, {%4,%5,%6,%7}, {%8,%9}, {%0,%1,%2,%3};" \
        : "+f"(c0), "+f"(c1), "+f"(c2), "+f"(c3) \
        : "r"(a0), "r"(a1), "r"(a2), "r"(a3), "r"(b0), "r"(b1))

__device__ __forceinline__ float fast_ex2(float x) { float y; asm("ex2.approx.ftz.f32 %0, %1;" : "=f"(y) : "f"(x)); return y; }
__device__ __forceinline__ float fast_sig(float x) { return __fdividef(1.f, 1.f + fast_ex2(-1.4426950408889634f * x)); }
__device__ __forceinline__ float fast_tanh(float x) {
    float ax = fabsf(x);
    float e = fast_ex2(-2.8853900817779268f * ax);
    float t = __fdividef(1.f - e, 1.f + e);
    return copysignf(t, x);
}
__device__ __forceinline__ void split_bf16(float v, __nv_bfloat16& hi, __nv_bfloat16& lo) {
    hi = __float2bfloat16(v);
    lo = __float2bfloat16(v - __bfloat162float(hi));
}

// ---------------- prep ----------------
__global__ __launch_bounds__(128) void prep_kernel(const float* __restrict__ U,
                                                   const float* __restrict__ h0,
                                                   const float* __restrict__ W,
                                                   const float* __restrict__ emb) {
    int blk = blockIdx.x;
    if (blk == 0 && threadIdx.x == 0) g_bar = 0;     // reset persistent barrier
    if (blk < kG) {                       // U^T gate-interleaved row n' = u*4+g
        int np = blk;
        int n = (np & 3) * kUnits + (np >> 2);
        for (int k = threadIdx.x; k < kUnits; k += 128) {
            __nv_bfloat16 hi, lo;
            split_bf16(__ldg(U + (size_t)k * kG + n), hi, lo);
            g_u_hi[np * kUnits + k] = hi;
            g_u_lo[np * kUnits + k] = lo;
        }
    } else if (blk < kG + 8) {            // h0 -> bf16 hi/lo into buffer 1
        int r0 = (blk - kG) * 64;
        for (int i = threadIdx.x; i < 64 * kUnits; i += 128) {
            int r = r0 + (i >> 9), k = i & 511;
            __nv_bfloat16 hi, lo;
            split_bf16(__ldg(h0 + (size_t)r * kUnits + k), hi, lo);
            g_hb_hi[1][r * kUnits + k] = hi;
            g_hb_lo[1][r * kUnits + k] = lo;
        }
    } else if (blk < kG + 8 + kG) {       // W^T row n, padded K
        int n = blk - kG - 8;
        for (int k = threadIdx.x; k < kEmbP; k += 128) {
            float v = (k < kEmbed) ? __ldg(W + (size_t)k * kG + n) : 0.f;
            __nv_bfloat16 hi, lo;
            split_bf16(v, hi, lo);
            g_wt_hi[n * kEmbP + k] = hi;
            g_wt_lo[n * kEmbP + k] = lo;
        }
    } else {                              // emb rows, padded
        int r0 = (blk - kG - 8 - kG) * 8;
        for (int rr = 0; rr < 8; rr++) {
            int row = r0 + rr;
            if (row >= kVocab) break;
            for (int k = threadIdx.x; k < kEmbP; k += 128) {
                float v = (k < kEmbed) ? __ldg(emb + (size_t)row * kEmbed + k) : 0.f;
                __nv_bfloat16 hi, lo;
                split_bf16(v, hi, lo);
                g_emb_hi[(size_t)row * kEmbP + k] = hi;
                g_emb_lo[(size_t)row * kEmbP + k] = lo;
            }
        }
    }
}

// ---------------- precompute Zpre via mma.sync (unchanged from R6 pass) ----------------
#define PC_STG 65536
#define PC_DYN 131072

extern "C" __global__ void __launch_bounds__(256, 1) precompute_mma_kernel(
    const int* __restrict__ seq, const float* __restrict__ bias)
{
    extern __shared__ __align__(1024) char smp[];
    const uint32_t smb = smem_u32(smp);
    __shared__ int toks[128];

    const int tid = threadIdx.x;
    const int wid = tid >> 5, lane = tid & 31;
    const int nt = blockIdx.x, b = blockIdx.y;
    const int n0 = nt * 128;

    if (tid < 128) toks[tid] = seq[(size_t)b * kT + tid];
    __syncthreads();

    const int wm = (wid & 1) * 64;
    const int wn = (wid >> 1) * 32;

    float acc[4][4][4];
#pragma unroll
    for (int i = 0; i < 4; i++)
#pragma unroll
        for (int j = 0; j < 4; j++)
#pragma unroll
            for (int q = 0; q < 4; q++) acc[i][j][q] = 0.f;

    auto issue_chunk = [&](int kc, int stg) {
#pragma unroll
        for (int i = 0; i < 16; i++) {
            int idx = i * 256 + tid;
            uint32_t dst;
            const __nv_bfloat16* src;
            if (idx < 2048) {
                int mat = idx >> 10, r = (idx >> 3) & 127, q = idx & 7;
                src = (mat ? g_emb_lo : g_emb_hi) + (size_t)toks[r] * kEmbP + kc * 64 + q * 8;
                uint32_t off = (uint32_t)(r * 128 + ((q ^ (r & 7)) * 16));
                dst = smb + stg * PC_STG + mat * 16384 + off;
            } else {
                int idxB = idx - 2048;
                int mat = idxB >> 10, r = (idxB >> 3) & 127, q = idxB & 7;
                src = (mat ? g_wt_lo : g_wt_hi) + (size_t)(n0 + r) * kEmbP + kc * 64 + q * 8;
                uint32_t off = (uint32_t)(r * 128 + ((q ^ (r & 7)) * 16));
                dst = smb + stg * PC_STG + 32768 + mat * 16384 + off;
            }
            CP_ASYNC16(dst, src);
        }
        CP_COMMIT();
    };

    issue_chunk(0, 0);

    const int la7 = lane & 7;
    const int arow_off = (lane >> 3) & 1;
    const int akseg   = (lane >> 4) & 1;
    const int brow_off = (lane >> 4) & 1;
    const int bkseg   = (lane >> 3) & 1;

    for (int kc = 0; kc < 5; kc++) {
        CP_WAIT0();
        __syncthreads();
        if (kc < 4) issue_chunk(kc + 1, (kc + 1) & 1);

        const uint32_t base = smb + (kc & 1) * PC_STG;
#pragma unroll
        for (int ks = 0; ks < 4; ks++) {
            uint32_t ahi[4][4], alo[4][4], bhi[2][4], blo[2][4];
#pragma unroll
            for (int mf = 0; mf < 4; mf++) {
                int row = wm + mf * 16 + la7 + arow_off * 8;
                uint32_t off = (uint32_t)(row * 128 + ks * 32 + akseg * 16);
                off ^= (uint32_t)((row & 7) * 16);
                LDMATRIX_X4(ahi[mf][0], ahi[mf][1], ahi[mf][2], ahi[mf][3], base + off);
                LDMATRIX_X4(alo[mf][0], alo[mf][1], alo[mf][2], alo[mf][3], base + 16384 + off);
            }
#pragma unroll
            for (int p = 0; p < 2; p++) {
                int row = wn + p * 16 + la7 + brow_off * 8;
                uint32_t off = (uint32_t)(row * 128 + ks * 32 + bkseg * 16);
                off ^= (uint32_t)((row & 7) * 16);
                LDMATRIX_X4(bhi[p][0], bhi[p][1], bhi[p][2], bhi[p][3], base + 32768 + off);
                LDMATRIX_X4(blo[p][0], blo[p][1], blo[p][2], blo[p][3], base + 49152 + off);
            }
#pragma unroll
            for (int mf = 0; mf < 4; mf++)
#pragma unroll
                for (int nf = 0; nf < 4; nf++) {
                    const int p = nf >> 1, s = (nf & 1) * 2;
                    float* c = acc[mf][nf];
                    MMA_BF16(c[0], c[1], c[2], c[3],
                             ahi[mf][0], ahi[mf][1], ahi[mf][2], ahi[mf][3],
                             bhi[p][s], bhi[p][s + 1]);
                    MMA_BF16(c[0], c[1], c[2], c[3],
                             ahi[mf][0], ahi[mf][1], ahi[mf][2], ahi[mf][3],
                             blo[p][s], blo[p][s + 1]);
                    MMA_BF16(c[0], c[1], c[2], c[3],
                             alo[mf][0], alo[mf][1], alo[mf][2], alo[mf][3],
                             bhi[p][s], bhi[p][s + 1]);
                }
        }
    }

    __syncthreads();
    float* zs = (float*)smp;
    {
        const int cr = lane >> 2, cc = (lane & 3) * 2;
#pragma unroll
        for (int mf = 0; mf < 4; mf++)
#pragma unroll
            for (int nf = 0; nf < 4; nf++) {
                int row = wm + mf * 16 + cr;
                int col = wn + nf * 8 + cc;
                *(float2*)&zs[row * 128 + col]       = make_float2(acc[mf][nf][0], acc[mf][nf][1]);
                *(float2*)&zs[(row + 8) * 128 + col] = make_float2(acc[mf][nf][2], acc[mf][nf][3]);
            }
    }
    __syncthreads();

    const int cseg = tid & 31;
    float4 bv = __ldg((const float4*)(bias + n0 + cseg * 4));
#pragma unroll
    for (int i = 0; i < 16; i++) {
        int r = i * 8 + (tid >> 5);
        float4 v = *(const float4*)&zs[r * 128 + cseg * 4];
        v.x += bv.x; v.y += bv.y; v.z += bv.z; v.w += bv.w;
        *(float4*)(g_zpre + ((size_t)b * kT + r) * kG + n0 + cseg * 4) = v;
    }
}

// ---------------- persistent LSTM recurrence ----------------
// grid (32 nt, 4 mt) = 128 CTAs (1/SM, all resident), 256 thr (8 warps 4x2).
// CTA tile: M=128 batch x N=64 n' (16 units x 4 gates). warp tile 32x32.
// SMEM: B (U slice) resident 128KB (hi+lo) + 3 A-stages x 32KB = 224KB.
// c and h kept in registers; global barrier between steps.
#define PK_BLO   65536
#define PK_ASTG  131072
#define PK_DYN   229376   /* 131072 + 3*32768 */

extern "C" __global__ void __launch_bounds__(256, 1) lstm_persist_kernel(
    const int* __restrict__ seq,
    const float* __restrict__ h0,
    const float* __restrict__ c0,
    float* __restrict__ out)
{
    extern __shared__ __align__(1024) char smp[];
    const uint32_t smb = smem_u32(smp);

    const int tid = threadIdx.x;
    const int wid = tid >> 5, lane = tid & 31;
    const int nt = blockIdx.x, mt = blockIdx.y;
    const int b0 = mt * 128;
    const int n0 = nt * 64;
    const int u0g = nt * 16;

    // ---- load resident B (U slice, hi+lo) ----
#pragma unroll
    for (int i = 0; i < 32; i++) {
        int idx = i * 256 + tid;            // 0..8191
        int mat = idx >> 12;
        int iu = idx & 4095;
        int r = iu >> 6, q = iu & 63;
        const __nv_bfloat16* src = (mat ? g_u_lo : g_u_hi) + (size_t)(n0 + r) * kUnits + q * 8;
        uint32_t off = (uint32_t)(r * 1024 + ((q * 16) ^ ((r & 7) * 16)));
        CP_ASYNC16(smb + mat * PK_BLO + off, src);
    }
    CP_COMMIT();

    // ---- per-thread cell state: 8 cells, r = it*16 + (tid>>4), ul = tid&15 ----
    const int rown = tid >> 4;     // 0..15
    const int ul = tid & 15;
    float creg[8], hreg[8], zpf[8][4];
    int seqv[8];
#pragma unroll
    for (int it = 0; it < 8; it++) {
        int b = b0 + it * 16 + rown;
        creg[it] = __ldg(c0 + (size_t)b * kUnits + u0g + ul);
        hreg[it] = __ldg(h0 + (size_t)b * kUnits + u0g + ul);
    }
    auto prefetch_z = [&](int t) {
#pragma unroll
        for (int it = 0; it < 8; it++) {
            int b = b0 + it * 16 + rown;
            const float* zp = g_zpre + ((size_t)b * kT + t) * kG;
#pragma unroll
            for (int g = 0; g < 4; g++)
                zpf[it][g] = __ldg(zp + g * kUnits + u0g + ul);
            seqv[it] = __ldg(seq + (size_t)b * kT + t);
        }
    };
    prefetch_z(0);

    CP_WAIT0();
    __syncthreads();   // B resident

    const int la7 = lane & 7;
    const int arow_off = (lane >> 3) & 1;
    const int akseg   = (lane >> 4) & 1;
    const int brow_off = (lane >> 4) & 1;
    const int bkseg   = (lane >> 3) & 1;
    const int wm = (wid & 3) * 32;      // A row block (128 rows / 4)
    const int wn = (wid >> 2) * 32;     // B row block (64 n' / 2)

    float* zs = (float*)(smp + PK_ASTG);   // 128 x 68 f32 staging (reuses A stages)

    for (int t = 0; t < kT; t++) {
        const __nv_bfloat16* srcA_hi = g_hb_hi[(t + 1) & 1] + (size_t)b0 * kUnits;
        const __nv_bfloat16* srcA_lo = g_hb_lo[(t + 1) & 1] + (size_t)b0 * kUnits;

        auto issueA = [&](int kc, int stg) {
#pragma unroll
            for (int i = 0; i < 8; i++) {
                int idx = i * 256 + tid;       // 0..2047
                int mat = idx >> 10;
                int iu = idx & 1023;
                int r = iu >> 3, q = iu & 7;
                const __nv_bfloat16* src =
                    (mat ? srcA_lo : srcA_hi) + (size_t)r * kUnits + kc * 64 + q * 8;
                uint32_t off = (uint32_t)(r * 128 + ((q ^ (r & 7)) * 16));
                CP_ASYNC16(smb + PK_ASTG + stg * 32768 + mat * 16384 + off, src);
            }
            CP_COMMIT();
        };

        float acc[2][4][4];
#pragma unroll
        for (int i = 0; i < 2; i++)
#pragma unroll
            for (int j = 0; j < 4; j++)
#pragma unroll
                for (int q = 0; q < 4; q++) acc[i][j][q] = 0.f;

        issueA(0, 0);
        issueA(1, 1);

        for (int kc = 0; kc < 8; kc++) {
            if (kc < 6) { CP_WAIT1(); } else { CP_WAIT0(); }
            __syncthreads();
            if (kc < 6) issueA(kc + 2, (kc + 2) % 3);

            const uint32_t aBase = smb + PK_ASTG + (kc % 3) * 32768;
            const int cb = kc * 128;
#pragma unroll
            for (int ks = 0; ks < 4; ks++) {
                uint32_t ahi[2][4], alo[2][4], bhi[2][4], blo[2][4];
#pragma unroll
                for (int mf = 0; mf < 2; mf++) {
                    int row = wm + mf * 16 + la7 + arow_off * 8;
                    uint32_t off = (uint32_t)(row * 128 +
                        ((ks * 32 + akseg * 16) ^ ((row & 7) * 16)));
                    LDMATRIX_X4(ahi[mf][0], ahi[mf][1], ahi[mf][2], ahi[mf][3], aBase + off);
                    LDMATRIX_X4(alo[mf][0], alo[mf][1], alo[mf][2], alo[mf][3], aBase + 16384 + off);
                }
#pragma unroll
                for (int p = 0; p < 2; p++) {
                    int row = wn + p * 16 + la7 + brow_off * 8;
                    uint32_t off = (uint32_t)(row * 1024 +
                        ((cb + ks * 32 + bkseg * 16) ^ ((row & 7) * 16)));
                    LDMATRIX_X4(bhi[p][0], bhi[p][1], bhi[p][2], bhi[p][3], smb + off);
                    LDMATRIX_X4(blo[p][0], blo[p][1], blo[p][2], blo[p][3], smb + PK_BLO + off);
                }
#pragma unroll
                for (int mf = 0; mf < 2; mf++)
#pragma unroll
                    for (int nf = 0; nf < 4; nf++) {
                        const int p = nf >> 1, s = (nf & 1) * 2;
                        float* c = acc[mf][nf];
                        MMA_BF16(c[0], c[1], c[2], c[3],
                                 ahi[mf][0], ahi[mf][1], ahi[mf][2], ahi[mf][3],
                                 bhi[p][s], bhi[p][s + 1]);
                        MMA_BF16(c[0], c[1], c[2], c[3],
                                 ahi[mf][0], ahi[mf][1], ahi[mf][2], ahi[mf][3],
                                 blo[p][s], blo[p][s + 1]);
                        MMA_BF16(c[0], c[1], c[2], c[3],
                                 alo[mf][0], alo[mf][1], alo[mf][2], alo[mf][3],
                                 bhi[p][s], bhi[p][s + 1]);
                    }
            }
        }

        // ---- stage z to smem (128 x 68 padded) ----
        __syncthreads();
        {
            const int cr = lane >> 2, cc = (lane & 3) * 2;
#pragma unroll
            for (int mf = 0; mf < 2; mf++)
#pragma unroll
                for (int nf = 0; nf < 4; nf++) {
                    int row = wm + mf * 16 + cr;
                    int col = wn + nf * 8 + cc;
                    *(float2*)&zs[row * 68 + col]       = make_float2(acc[mf][nf][0], acc[mf][nf][1]);
                    *(float2*)&zs[(row + 8) * 68 + col] = make_float2(acc[mf][nf][2], acc[mf][nf][3]);
                }
        }
        __syncthreads();

        // ---- fused LSTM epilogue (state in registers) ----
        __nv_bfloat16* dsthi = g_hb_hi[t & 1];
        __nv_bfloat16* dstlo = g_hb_lo[t & 1];
#pragma unroll
        for (int it = 0; it < 8; it++) {
            int r = it * 16 + rown;
            int b = b0 + r;
            int u = u0g + ul;
            float4 z4 = *(const float4*)&zs[r * 68 + ul * 4];
            float zi = z4.x + zpf[it][0];
            float zf = z4.y + zpf[it][1];
            float zg = z4.z + zpf[it][2];
            float zo = z4.w + zpf[it][3];
            float ig = fast_sig(zi);
            float fg = fast_sig(zf);
            float og = fast_sig(zo);
            float cnew = fmaf(fg, creg[it], ig * fast_tanh(zg));
            float hnew = og * fast_tanh(cnew);
            if (seqv[it] == 0) { cnew = creg[it]; hnew = hreg[it]; }
            creg[it] = cnew;
            hreg[it] = hnew;
            out[(size_t)b * (kT * kUnits) + (size_t)t * kUnits + u] = hnew;
            __nv_bfloat16 hi, lo;
            split_bf16(hnew, hi, lo);
            dsthi[(size_t)b * kUnits + u] = hi;
            dstlo[(size_t)b * kUnits + u] = lo;
        }

        if (t == kT - 1) {
            float* hfin = out + (size_t)kB * kT * kUnits;
            float* cfin = hfin + (size_t)kB * kUnits;
#pragma unroll
            for (int it = 0; it < 8; it++) {
                int b = b0 + it * 16 + rown;
                hfin[(size_t)b * kUnits + u0g + ul] = hreg[it];
                cfin[(size_t)b * kUnits + u0g + ul] = creg[it];
            }
            break;
        }

        // prefetch next step's zpre/seq before waiting (hides DRAM latency)
        prefetch_z(t + 1);

        // ---- global barrier ----
        __threadfence();
        __syncthreads();
        if (tid == 0) {
            asm volatile("red.release.gpu.global.add.u32 [%0], 1;"
                         :: "l"(&g_bar) : "memory");
            unsigned target = 128u * (unsigned)(t + 1);
            unsigned v;
            do {
                asm volatile("ld.acquire.gpu.global.u32 %0, [%1];"
                             : "=r"(v) : "l"(&g_bar) : "memory");
                if (v < target) __nanosleep(64);
            } while (v < target);
        }
        __syncthreads();
    }
}

// ---------------- host ----------------
extern "C" void kernel_launch(void* const* d_in, const int* in_sizes, int n_in,
                              void* d_out, int out_size)
{
    const int*   seq  = (const int*)d_in[0];
    const float* h0   = (const float*)d_in[1];
    const float* c0   = (const float*)d_in[2];
    const float* emb  = (const float*)d_in[3];
    const float* W    = (const float*)d_in[4];
    const float* Umat = (const float*)d_in[5];
    const float* bias = (const float*)d_in[6];
    float* out = (float*)d_out;

    static int configured = 0;
    if (!configured) {
        cudaFuncSetAttribute(precompute_mma_kernel, cudaFuncAttributeMaxDynamicSharedMemorySize, PC_DYN);
        cudaFuncSetAttribute(lstm_persist_kernel, cudaFuncAttributeMaxDynamicSharedMemorySize, PK_DYN);
        configured = 1;
    }

    const int embBlocks = (kVocab + 7) / 8;
    prep_kernel<<<kG + 8 + kG + embBlocks, 128>>>(Umat, h0, W, emb);

    precompute_mma_kernel<<<dim3(16, kB), 256, PC_DYN>>>(seq, bias);

    lstm_persist_kernel<<<dim3(32, 4), 256, PK_DYN>>>(seq, h0, c0, out);
}

// round 8
// speedup vs baseline: 1.0301x; 1.0301x over previous
#include <cuda_runtime.h>
#include <cuda_bf16.h>
#include <cstdint>
#include <math.h>

#define kVocab 50000
#define kEmbed 300
#define kEmbP  320
#define kUnits 512
#define kT 128
#define kB 512
#define kG 2048

// ---------------- global scratch ----------------
__device__ float g_zpre[(size_t)kB * kT * kG];
__device__ float g_c[(size_t)kB * kUnits];
__device__ __align__(128) __nv_bfloat16 g_u_hi[kG * kUnits];
__device__ __align__(128) __nv_bfloat16 g_u_lo[kG * kUnits];
__device__ __align__(128) __nv_bfloat16 g_hb_hi[2][kB * kUnits];
__device__ __align__(128) __nv_bfloat16 g_hb_lo[2][kB * kUnits];
__device__ __align__(128) __nv_bfloat16 g_emb_hi[(size_t)kVocab * kEmbP];
__device__ __align__(128) __nv_bfloat16 g_emb_lo[(size_t)kVocab * kEmbP];
__device__ __align__(128) __nv_bfloat16 g_wt_hi[kG * kEmbP];
__device__ __align__(128) __nv_bfloat16 g_wt_lo[kG * kEmbP];

// ---------------- helpers ----------------
__device__ __forceinline__ uint32_t smem_u32(const void* p) {
    uint32_t a;
    asm("{ .reg .u64 t; cvta.to.shared.u64 t, %1; cvt.u32.u64 %0, t; }" : "=r"(a) : "l"(p));
    return a;
}
#define CP_ASYNC16(dst, src) \
    asm volatile("cp.async.ca.shared.global [%0], [%1], 16;" :: "r"(dst), "l"(src) : "memory")
#define CP_COMMIT() asm volatile("cp.async.commit_group;" ::: "memory")
#define CP_WAIT0()  asm volatile("cp.async.wait_group 0;" ::: "memory")
#define CP_WAIT1()  asm volatile("cp.async.wait_group 1;" ::: "memory")

#define LDMATRIX_X4(r0, r1, r2, r3, addr) \
    asm volatile("ldmatrix.sync.aligned.m8n8.x4.shared.b16 {%0,%1,%2,%3}, [%4];" \
        : "=r"(r0), "=r"(r1), "=r"(r2), "=r"(r3) : "r"(addr))

#define MMA_BF16(c0, c1, c2, c3, a0, a1, a2, a3, b0, b1) \
    asm volatile("mma.sync.aligned.m16n8k16.row.col.f32.bf16.bf16.f32 " \
        "{%0,%1,%2,%3}, {%4,%5,%6,%7}, {%8,%9}, {%0,%1,%2,%3};" \
        : "+f"(c0), "+f"(c1), "+f"(c2), "+f"(c3) \
        : "r"(a0), "r"(a1), "r"(a2), "r"(a3), "r"(b0), "r"(b1))

__device__ __forceinline__ float fast_ex2(float x) { float y; asm("ex2.approx.ftz.f32 %0, %1;" : "=f"(y) : "f"(x)); return y; }
__device__ __forceinline__ float fast_sig(float x) { return __fdividef(1.f, 1.f + fast_ex2(-1.4426950408889634f * x)); }
__device__ __forceinline__ float fast_tanh(float x) {
    float ax = fabsf(x);
    float e = fast_ex2(-2.8853900817779268f * ax);
    float t = __fdividef(1.f - e, 1.f + e);
    return copysignf(t, x);
}
__device__ __forceinline__ void split_bf16(float v, __nv_bfloat16& hi, __nv_bfloat16& lo) {
    hi = __float2bfloat16(v);
    lo = __float2bfloat16(v - __bfloat162float(hi));
}

// ---------------- prep ----------------
__global__ __launch_bounds__(128) void prep_kernel(const float* __restrict__ U,
                                                   const float* __restrict__ h0,
                                                   const float* __restrict__ W,
                                                   const float* __restrict__ emb) {
    int blk = blockIdx.x;
    if (blk < kG) {
        int np = blk;
        int n = (np & 3) * kUnits + (np >> 2);
        for (int k = threadIdx.x; k < kUnits; k += 128) {
            __nv_bfloat16 hi, lo;
            split_bf16(__ldg(U + (size_t)k * kG + n), hi, lo);
            g_u_hi[np * kUnits + k] = hi;
            g_u_lo[np * kUnits + k] = lo;
        }
    } else if (blk < kG + 8) {
        int r0 = (blk - kG) * 64;
        for (int i = threadIdx.x; i < 64 * kUnits; i += 128) {
            int r = r0 + (i >> 9), k = i & 511;
            __nv_bfloat16 hi, lo;
            split_bf16(__ldg(h0 + (size_t)r * kUnits + k), hi, lo);
            g_hb_hi[1][r * kUnits + k] = hi;
            g_hb_lo[1][r * kUnits + k] = lo;
        }
    } else if (blk < kG + 8 + kG) {
        int n = blk - kG - 8;
        for (int k = threadIdx.x; k < kEmbP; k += 128) {
            float v = (k < kEmbed) ? __ldg(W + (size_t)k * kG + n) : 0.f;
            __nv_bfloat16 hi, lo;
            split_bf16(v, hi, lo);
            g_wt_hi[n * kEmbP + k] = hi;
            g_wt_lo[n * kEmbP + k] = lo;
        }
    } else {
        int r0 = (blk - kG - 8 - kG) * 8;
        for (int rr = 0; rr < 8; rr++) {
            int row = r0 + rr;
            if (row >= kVocab) break;
            for (int k = threadIdx.x; k < kEmbP; k += 128) {
                float v = (k < kEmbed) ? __ldg(emb + (size_t)row * kEmbed + k) : 0.f;
                __nv_bfloat16 hi, lo;
                split_bf16(v, hi, lo);
                g_emb_hi[(size_t)row * kEmbP + k] = hi;
                g_emb_lo[(size_t)row * kEmbP + k] = lo;
            }
        }
    }
}

// ---------------- precompute Zpre via mma.sync (R6, proven) ----------------
#define PC_STG 65536
#define PC_DYN 131072

extern "C" __global__ void __launch_bounds__(256, 1) precompute_mma_kernel(
    const int* __restrict__ seq, const float* __restrict__ bias)
{
    extern __shared__ __align__(1024) char smp[];
    const uint32_t smb = smem_u32(smp);
    __shared__ int toks[128];

    const int tid = threadIdx.x;
    const int wid = tid >> 5, lane = tid & 31;
    const int nt = blockIdx.x, b = blockIdx.y;
    const int n0 = nt * 128;

    if (tid < 128) toks[tid] = seq[(size_t)b * kT + tid];
    __syncthreads();

    const int wm = (wid & 1) * 64;
    const int wn = (wid >> 1) * 32;

    float acc[4][4][4];
#pragma unroll
    for (int i = 0; i < 4; i++)
#pragma unroll
        for (int j = 0; j < 4; j++)
#pragma unroll
            for (int q = 0; q < 4; q++) acc[i][j][q] = 0.f;

    auto issue_chunk = [&](int kc, int stg) {
#pragma unroll
        for (int i = 0; i < 16; i++) {
            int idx = i * 256 + tid;
            uint32_t dst;
            const __nv_bfloat16* src;
            if (idx < 2048) {
                int mat = idx >> 10, r = (idx >> 3) & 127, q = idx & 7;
                src = (mat ? g_emb_lo : g_emb_hi) + (size_t)toks[r] * kEmbP + kc * 64 + q * 8;
                uint32_t off = (uint32_t)(r * 128 + ((q ^ (r & 7)) * 16));
                dst = smb + stg * PC_STG + mat * 16384 + off;
            } else {
                int idxB = idx - 2048;
                int mat = idxB >> 10, r = (idxB >> 3) & 127, q = idxB & 7;
                src = (mat ? g_wt_lo : g_wt_hi) + (size_t)(n0 + r) * kEmbP + kc * 64 + q * 8;
                uint32_t off = (uint32_t)(r * 128 + ((q ^ (r & 7)) * 16));
                dst = smb + stg * PC_STG + 32768 + mat * 16384 + off;
            }
            CP_ASYNC16(dst, src);
        }
        CP_COMMIT();
    };

    issue_chunk(0, 0);

    const int la7 = lane & 7;
    const int arow_off = (lane >> 3) & 1;
    const int akseg   = (lane >> 4) & 1;
    const int brow_off = (lane >> 4) & 1;
    const int bkseg   = (lane >> 3) & 1;

    for (int kc = 0; kc < 5; kc++) {
        CP_WAIT0();
        __syncthreads();
        if (kc < 4) issue_chunk(kc + 1, (kc + 1) & 1);

        const uint32_t base = smb + (kc & 1) * PC_STG;
#pragma unroll
        for (int ks = 0; ks < 4; ks++) {
            uint32_t ahi[4][4], alo[4][4], bhi[2][4], blo[2][4];
#pragma unroll
            for (int mf = 0; mf < 4; mf++) {
                int row = wm + mf * 16 + la7 + arow_off * 8;
                uint32_t off = (uint32_t)(row * 128 + ks * 32 + akseg * 16);
                off ^= (uint32_t)((row & 7) * 16);
                LDMATRIX_X4(ahi[mf][0], ahi[mf][1], ahi[mf][2], ahi[mf][3], base + off);
                LDMATRIX_X4(alo[mf][0], alo[mf][1], alo[mf][2], alo[mf][3], base + 16384 + off);
            }
#pragma unroll
            for (int p = 0; p < 2; p++) {
                int row = wn + p * 16 + la7 + brow_off * 8;
                uint32_t off = (uint32_t)(row * 128 + ks * 32 + bkseg * 16);
                off ^= (uint32_t)((row & 7) * 16);
                LDMATRIX_X4(bhi[p][0], bhi[p][1], bhi[p][2], bhi[p][3], base + 32768 + off);
                LDMATRIX_X4(blo[p][0], blo[p][1], blo[p][2], blo[p][3], base + 49152 + off);
            }
#pragma unroll
            for (int mf = 0; mf < 4; mf++)
#pragma unroll
                for (int nf = 0; nf < 4; nf++) {
                    const int p = nf >> 1, s = (nf & 1) * 2;
                    float* c = acc[mf][nf];
                    MMA_BF16(c[0], c[1], c[2], c[3],
                             ahi[mf][0], ahi[mf][1], ahi[mf][2], ahi[mf][3],
                             bhi[p][s], bhi[p][s + 1]);
                    MMA_BF16(c[0], c[1], c[2], c[3],
                             ahi[mf][0], ahi[mf][1], ahi[mf][2], ahi[mf][3],
                             blo[p][s], blo[p][s + 1]);
                    MMA_BF16(c[0], c[1], c[2], c[3],
                             alo[mf][0], alo[mf][1], alo[mf][2], alo[mf][3],
                             bhi[p][s], bhi[p][s + 1]);
                }
        }
    }

    __syncthreads();
    float* zs = (float*)smp;
    {
        const int cr = lane >> 2, cc = (lane & 3) * 2;
#pragma unroll
        for (int mf = 0; mf < 4; mf++)
#pragma unroll
            for (int nf = 0; nf < 4; nf++) {
                int row = wm + mf * 16 + cr;
                int col = wn + nf * 8 + cc;
                *(float2*)&zs[row * 128 + col]       = make_float2(acc[mf][nf][0], acc[mf][nf][1]);
                *(float2*)&zs[(row + 8) * 128 + col] = make_float2(acc[mf][nf][2], acc[mf][nf][3]);
            }
    }
    __syncthreads();

    const int cseg = tid & 31;
    float4 bv = __ldg((const float4*)(bias + n0 + cseg * 4));
#pragma unroll
    for (int i = 0; i < 16; i++) {
        int r = i * 8 + (tid >> 5);
        float4 v = *(const float4*)&zs[r * 128 + cseg * 4];
        v.x += bv.x; v.y += bv.y; v.z += bv.z; v.w += bv.w;
        *(float4*)(g_zpre + ((size_t)b * kT + r) * kG + n0 + cseg * 4) = v;
    }
}

// ---------------- mma.sync LSTM step: 512 threads / 16 warps ----------------
// grid (16 nt, 8 mt) = 128 CTAs. CTA tile M=64 x N=128, K=512 in 8 chunks of 64.
// 16 warps as 2(m) x 8(n), warp tile 32x16; acc[2][2][4].
// smem: 3 stages x 48KB = 144KB (A hi/lo 16KB + B hi/lo 32KB per stage).
#define ST_STG 49152
#define ST_DYN 147456

extern "C" __global__ void __launch_bounds__(512, 1) step_mma_kernel(
    int t,
    const int* __restrict__ seq,
    const float* __restrict__ hprev_f32, int hstride,
    const float* __restrict__ c0,
    float* __restrict__ out)
{
    extern __shared__ __align__(1024) char smp[];
    const uint32_t smb = smem_u32(smp);

    const int tid = threadIdx.x;
    const int wid = tid >> 5, lane = tid & 31;
    const int nt = blockIdx.x, mt = blockIdx.y;
    const int b0 = mt * 64;
    const int n0 = nt * 128;
    const int u0g = nt * 32;

    // ---- epilogue operand prefetch (overlaps GEMM): 4 cells per thread ----
    const int ul = tid & 31;          // unit within 32
    const int rw = tid >> 5;          // 0..15
    float zpf[4][4], cpre[4];
    int seqv[4];
    {
        const float* cin = (t == 0) ? c0 : g_c;
#pragma unroll
        for (int it = 0; it < 4; it++) {
            int bb = b0 + it * 16 + rw;
            const float* zp = g_zpre + ((size_t)bb * kT + t) * kG;
#pragma unroll
            for (int g = 0; g < 4; g++)
                zpf[it][g] = __ldg(zp + g * kUnits + u0g + ul);
            cpre[it] = __ldg(cin + (size_t)bb * kUnits + u0g + ul);
            seqv[it] = __ldg(seq + (size_t)bb * kT + t);
        }
    }

    const __nv_bfloat16* srcA_hi = g_hb_hi[(t + 1) & 1] + (size_t)b0 * kUnits;
    const __nv_bfloat16* srcA_lo = g_hb_lo[(t + 1) & 1] + (size_t)b0 * kUnits;
    const __nv_bfloat16* srcB_hi = g_u_hi + (size_t)n0 * kUnits;
    const __nv_bfloat16* srcB_lo = g_u_lo + (size_t)n0 * kUnits;

    const int wm = (wid & 1) * 32;      // 2 m-warps
    const int wn = (wid >> 1) * 16;     // 8 n-warps

    float acc[2][2][4];
#pragma unroll
    for (int i = 0; i < 2; i++)
#pragma unroll
        for (int j = 0; j < 2; j++)
#pragma unroll
            for (int q = 0; q < 4; q++) acc[i][j][q] = 0.f;

    auto issue_chunk = [&](int kc, int stg) {
#pragma unroll
        for (int i = 0; i < 6; i++) {
            int idx = i * 512 + tid;
            uint32_t dst;
            const __nv_bfloat16* src;
            if (idx < 1024) {         // A: 64 rows, hi/lo
                int mat = idx >> 9, r = (idx >> 3) & 63, q = idx & 7;
                src = (mat ? srcA_lo : srcA_hi) + (size_t)r * kUnits + kc * 64 + q * 8;
                uint32_t off = (uint32_t)(r * 128 + ((q ^ (r & 7)) * 16));
                dst = smb + stg * ST_STG + mat * 8192 + off;
            } else {                  // B: 128 rows, hi/lo
                int idxB = idx - 1024;
                int mat = idxB >> 10, r = (idxB >> 3) & 127, q = idxB & 7;
                src = (mat ? srcB_lo : srcB_hi) + (size_t)r * kUnits + kc * 64 + q * 8;
                uint32_t off = (uint32_t)(r * 128 + ((q ^ (r & 7)) * 16));
                dst = smb + stg * ST_STG + 16384 + mat * 16384 + off;
            }
            CP_ASYNC16(dst, src);
        }
        CP_COMMIT();
    };

    issue_chunk(0, 0);
    issue_chunk(1, 1);

    const int la7 = lane & 7;
    const int arow_off = (lane >> 3) & 1;
    const int akseg   = (lane >> 4) & 1;
    const int brow_off = (lane >> 4) & 1;
    const int bkseg   = (lane >> 3) & 1;

    for (int kc = 0; kc < 8; kc++) {
        if (kc < 6) { CP_WAIT1(); } else { CP_WAIT0(); }
        __syncthreads();
        if (kc < 6) issue_chunk(kc + 2, (kc + 2) % 3);

        const uint32_t base = smb + (kc % 3) * ST_STG;
#pragma unroll
        for (int ks = 0; ks < 4; ks++) {
            uint32_t ahi[2][4], alo[2][4], bhi[4], blo[4];
#pragma unroll
            for (int mf = 0; mf < 2; mf++) {
                int row = wm + mf * 16 + la7 + arow_off * 8;
                uint32_t off = (uint32_t)(row * 128 + ks * 32 + akseg * 16);
                off ^= (uint32_t)((row & 7) * 16);
                LDMATRIX_X4(ahi[mf][0], ahi[mf][1], ahi[mf][2], ahi[mf][3], base + off);
                LDMATRIX_X4(alo[mf][0], alo[mf][1], alo[mf][2], alo[mf][3], base + 8192 + off);
            }
            {
                int row = wn + la7 + brow_off * 8;
                uint32_t off = (uint32_t)(row * 128 + ks * 32 + bkseg * 16);
                off ^= (uint32_t)((row & 7) * 16);
                LDMATRIX_X4(bhi[0], bhi[1], bhi[2], bhi[3], base + 16384 + off);
                LDMATRIX_X4(blo[0], blo[1], blo[2], blo[3], base + 32768 + off);
            }
#pragma unroll
            for (int mf = 0; mf < 2; mf++)
#pragma unroll
                for (int nf = 0; nf < 2; nf++) {
                    const int s = nf * 2;
                    float* c = acc[mf][nf];
                    MMA_BF16(c[0], c[1], c[2], c[3],
                             ahi[mf][0], ahi[mf][1], ahi[mf][2], ahi[mf][3],
                             bhi[s], bhi[s + 1]);
                    MMA_BF16(c[0], c[1], c[2], c[3],
                             ahi[mf][0], ahi[mf][1], ahi[mf][2], ahi[mf][3],
                             blo[s], blo[s + 1]);
                    MMA_BF16(c[0], c[1], c[2], c[3],
                             alo[mf][0], alo[mf][1], alo[mf][2], alo[mf][3],
                             bhi[s], bhi[s + 1]);
                }
        }
    }

    // ---- stage z to smem: 64x128 f32 = 32KB (reuse stage 0) ----
    __syncthreads();
    float* zs = (float*)smp;
    {
        const int cr = lane >> 2, cc = (lane & 3) * 2;
#pragma unroll
        for (int mf = 0; mf < 2; mf++)
#pragma unroll
            for (int nf = 0; nf < 2; nf++) {
                int row = wm + mf * 16 + cr;
                int col = wn + nf * 8 + cc;
                *(float2*)&zs[row * 128 + col]       = make_float2(acc[mf][nf][0], acc[mf][nf][1]);
                *(float2*)&zs[(row + 8) * 128 + col] = make_float2(acc[mf][nf][2], acc[mf][nf][3]);
            }
    }
    __syncthreads();

    // ---- fused LSTM epilogue: 64 rows x 32 units, 4 cells/thread ----
    __nv_bfloat16* dsthi = g_hb_hi[t & 1];
    __nv_bfloat16* dstlo = g_hb_lo[t & 1];
#pragma unroll
    for (int it = 0; it < 4; it++) {
        int r = it * 16 + rw;
        int b = b0 + r;
        int u = u0g + ul;
        float4 z4 = *(const float4*)&zs[r * 128 + ul * 4];
        float zi = z4.x + zpf[it][0];
        float zf = z4.y + zpf[it][1];
        float zg = z4.z + zpf[it][2];
        float zo = z4.w + zpf[it][3];
        float ig = fast_sig(zi);
        float fg = fast_sig(zf);
        float og = fast_sig(zo);
        float cold = cpre[it];
        float cnew = fmaf(fg, cold, ig * fast_tanh(zg));
        float hnew = og * fast_tanh(cnew);
        if (seqv[it] == 0) {
            cnew = cold;
            hnew = __ldg(hprev_f32 + (size_t)b * hstride + u);
        }
        g_c[(size_t)b * kUnits + u] = cnew;
        out[(size_t)b * (kT * kUnits) + (size_t)t * kUnits + u] = hnew;
        __nv_bfloat16 hi, lo;
        split_bf16(hnew, hi, lo);
        dsthi[(size_t)b * kUnits + u] = hi;
        dstlo[(size_t)b * kUnits + u] = lo;
    }
}

// ---------------- finalize ----------------
__global__ __launch_bounds__(256) void finalize_kernel(float* __restrict__ out)
{
    int i = blockIdx.x * blockDim.x + threadIdx.x;
    if (i < kB * kUnits) {
        int b = i / kUnits;
        int u = i - b * kUnits;
        float* hfin = out + (size_t)kB * kT * kUnits;
        float* cfin = hfin + (size_t)kB * kUnits;
        hfin[i] = out[(size_t)b * (kT * kUnits) + (size_t)(kT - 1) * kUnits + u];
        cfin[i] = g_c[i];
    }
}

// ---------------- host ----------------
extern "C" void kernel_launch(void* const* d_in, const int* in_sizes, int n_in,
                              void* d_out, int out_size)
{
    const int*   seq  = (const int*)d_in[0];
    const float* h0   = (const float*)d_in[1];
    const float* c0   = (const float*)d_in[2];
    const float* emb  = (const float*)d_in[3];
    const float* W    = (const float*)d_in[4];
    const float* Umat = (const float*)d_in[5];
    const float* bias = (const float*)d_in[6];
    float* out = (float*)d_out;

    static int configured = 0;
    if (!configured) {
        cudaFuncSetAttribute(precompute_mma_kernel, cudaFuncAttributeMaxDynamicSharedMemorySize, PC_DYN);
        cudaFuncSetAttribute(step_mma_kernel, cudaFuncAttributeMaxDynamicSharedMemorySize, ST_DYN);
        configured = 1;
    }

    const int embBlocks = (kVocab + 7) / 8;
    prep_kernel<<<kG + 8 + kG + embBlocks, 128>>>(Umat, h0, W, emb);

    precompute_mma_kernel<<<dim3(16, kB), 256, PC_DYN>>>(seq, bias);

    for (int t = 0; t < kT; t++) {
        const float* hprev = t ? (out + (size_t)(t - 1) * kUnits) : h0;
        int hstride = t ? (kT * kUnits) : kUnits;
        step_mma_kernel<<<dim3(16, 8), 512, ST_DYN>>>(t, seq, hprev, hstride, c0, out);
    }

    finalize_kernel<<<(kB * kUnits + 255) / 256, 256>>>(out);
}

// round 9
// speedup vs baseline: 1.0558x; 1.0249x over previous
#include <cuda_runtime.h>
#include <cuda_bf16.h>
#include <cstdint>
#include <math.h>

#define kVocab 50000
#define kEmbed 300
#define kEmbP  320
#define kUnits 512
#define kT 128
#define kB 512
#define kG 2048

// ---------------- global scratch ----------------
__device__ float g_zpre[(size_t)kB * kT * kG];
__device__ float g_c[(size_t)kB * kUnits];
__device__ __align__(128) __nv_bfloat16 g_u_hi[kG * kUnits];
__device__ __align__(128) __nv_bfloat16 g_u_lo[kG * kUnits];
__device__ __align__(128) __nv_bfloat16 g_hb_hi[2][kB * kUnits];
__device__ __align__(128) __nv_bfloat16 g_hb_lo[2][kB * kUnits];
__device__ __align__(128) __nv_bfloat16 g_emb_hi[(size_t)kVocab * kEmbP];
__device__ __align__(128) __nv_bfloat16 g_emb_lo[(size_t)kVocab * kEmbP];
__device__ __align__(128) __nv_bfloat16 g_wt_hi[kG * kEmbP];
__device__ __align__(128) __nv_bfloat16 g_wt_lo[kG * kEmbP];

// ---------------- helpers ----------------
__device__ __forceinline__ uint32_t smem_u32(const void* p) {
    uint32_t a;
    asm("{ .reg .u64 t; cvta.to.shared.u64 t, %1; cvt.u32.u64 %0, t; }" : "=r"(a) : "l"(p));
    return a;
}
#define CP_ASYNC16(dst, src) \
    asm volatile("cp.async.ca.shared.global [%0], [%1], 16;" :: "r"(dst), "l"(src) : "memory")
#define CP_COMMIT() asm volatile("cp.async.commit_group;" ::: "memory")
#define CP_WAIT0()  asm volatile("cp.async.wait_group 0;" ::: "memory")

#define LDMATRIX_X4(r0, r1, r2, r3, addr) \
    asm volatile("ldmatrix.sync.aligned.m8n8.x4.shared.b16 {%0,%1,%2,%3}, [%4];" \
        : "=r"(r0), "=r"(r1), "=r"(r2), "=r"(r3) : "r"(addr))

#define MMA_BF16(c0, c1, c2, c3, a0, a1, a2, a3, b0, b1) \
    asm volatile("mma.sync.aligned.m16n8k16.row.col.f32.bf16.bf16.f32 " \
        "{%0,%1,%2,%3}, {%4,%5,%6,%7}, {%8,%9}, {%0,%1,%2,%3};" \
        : "+f"(c0), "+f"(c1), "+f"(c2), "+f"(c3) \
        : "r"(a0), "r"(a1), "r"(a2), "r"(a3), "r"(b0), "r"(b1))

__device__ __forceinline__ float fast_ex2(float x) { float y; asm("ex2.approx.ftz.f32 %0, %1;" : "=f"(y) : "f"(x)); return y; }
__device__ __forceinline__ float fast_sig(float x) { return __fdividef(1.f, 1.f + fast_ex2(-1.4426950408889634f * x)); }
__device__ __forceinline__ float fast_tanh(float x) {
    float ax = fabsf(x);
    float e = fast_ex2(-2.8853900817779268f * ax);
    float t = __fdividef(1.f - e, 1.f + e);
    return copysignf(t, x);
}
__device__ __forceinline__ void split_bf16(float v, __nv_bfloat16& hi, __nv_bfloat16& lo) {
    hi = __float2bfloat16(v);
    lo = __float2bfloat16(v - __bfloat162float(hi));
}

// ---------------- prep ----------------
__global__ __launch_bounds__(128) void prep_kernel(const float* __restrict__ U,
                                                   const float* __restrict__ h0,
                                                   const float* __restrict__ W,
                                                   const float* __restrict__ emb) {
    int blk = blockIdx.x;
    if (blk < kG) {
        int np = blk;
        int n = (np & 3) * kUnits + (np >> 2);
        for (int k = threadIdx.x; k < kUnits; k += 128) {
            __nv_bfloat16 hi, lo;
            split_bf16(__ldg(U + (size_t)k * kG + n), hi, lo);
            g_u_hi[np * kUnits + k] = hi;
            g_u_lo[np * kUnits + k] = lo;
        }
    } else if (blk < kG + 8) {
        int r0 = (blk - kG) * 64;
        for (int i = threadIdx.x; i < 64 * kUnits; i += 128) {
            int r = r0 + (i >> 9), k = i & 511;
            __nv_bfloat16 hi, lo;
            split_bf16(__ldg(h0 + (size_t)r * kUnits + k), hi, lo);
            g_hb_hi[1][r * kUnits + k] = hi;
            g_hb_lo[1][r * kUnits + k] = lo;
        }
    } else if (blk < kG + 8 + kG) {
        int n = blk - kG - 8;
        for (int k = threadIdx.x; k < kEmbP; k += 128) {
            float v = (k < kEmbed) ? __ldg(W + (size_t)k * kG + n) : 0.f;
            __nv_bfloat16 hi, lo;
            split_bf16(v, hi, lo);
            g_wt_hi[n * kEmbP + k] = hi;
            g_wt_lo[n * kEmbP + k] = lo;
        }
    } else {
        int r0 = (blk - kG - 8 - kG) * 8;
        for (int rr = 0; rr < 8; rr++) {
            int row = r0 + rr;
            if (row >= kVocab) break;
            for (int k = threadIdx.x; k < kEmbP; k += 128) {
                float v = (k < kEmbed) ? __ldg(emb + (size_t)row * kEmbed + k) : 0.f;
                __nv_bfloat16 hi, lo;
                split_bf16(v, hi, lo);
                g_emb_hi[(size_t)row * kEmbP + k] = hi;
                g_emb_lo[(size_t)row * kEmbP + k] = lo;
            }
        }
    }
}

// ---------------- precompute Zpre via mma.sync (R6, proven) ----------------
#define PC_STG 65536
#define PC_DYN 131072

extern "C" __global__ void __launch_bounds__(256, 1) precompute_mma_kernel(
    const int* __restrict__ seq, const float* __restrict__ bias)
{
    extern __shared__ __align__(1024) char smp[];
    const uint32_t smb = smem_u32(smp);
    __shared__ int toks[128];

    const int tid = threadIdx.x;
    const int wid = tid >> 5, lane = tid & 31;
    const int nt = blockIdx.x, b = blockIdx.y;
    const int n0 = nt * 128;

    if (tid < 128) toks[tid] = seq[(size_t)b * kT + tid];
    __syncthreads();

    const int wm = (wid & 1) * 64;
    const int wn = (wid >> 1) * 32;

    float acc[4][4][4];
#pragma unroll
    for (int i = 0; i < 4; i++)
#pragma unroll
        for (int j = 0; j < 4; j++)
#pragma unroll
            for (int q = 0; q < 4; q++) acc[i][j][q] = 0.f;

    auto issue_chunk = [&](int kc, int stg) {
#pragma unroll
        for (int i = 0; i < 16; i++) {
            int idx = i * 256 + tid;
            uint32_t dst;
            const __nv_bfloat16* src;
            if (idx < 2048) {
                int mat = idx >> 10, r = (idx >> 3) & 127, q = idx & 7;
                src = (mat ? g_emb_lo : g_emb_hi) + (size_t)toks[r] * kEmbP + kc * 64 + q * 8;
                uint32_t off = (uint32_t)(r * 128 + ((q ^ (r & 7)) * 16));
                dst = smb + stg * PC_STG + mat * 16384 + off;
            } else {
                int idxB = idx - 2048;
                int mat = idxB >> 10, r = (idxB >> 3) & 127, q = idxB & 7;
                src = (mat ? g_wt_lo : g_wt_hi) + (size_t)(n0 + r) * kEmbP + kc * 64 + q * 8;
                uint32_t off = (uint32_t)(r * 128 + ((q ^ (r & 7)) * 16));
                dst = smb + stg * PC_STG + 32768 + mat * 16384 + off;
            }
            CP_ASYNC16(dst, src);
        }
        CP_COMMIT();
    };

    issue_chunk(0, 0);

    const int la7 = lane & 7;
    const int arow_off = (lane >> 3) & 1;
    const int akseg   = (lane >> 4) & 1;
    const int brow_off = (lane >> 4) & 1;
    const int bkseg   = (lane >> 3) & 1;

    for (int kc = 0; kc < 5; kc++) {
        CP_WAIT0();
        __syncthreads();
        if (kc < 4) issue_chunk(kc + 1, (kc + 1) & 1);

        const uint32_t base = smb + (kc & 1) * PC_STG;
#pragma unroll
        for (int ks = 0; ks < 4; ks++) {
            uint32_t ahi[4][4], alo[4][4], bhi[2][4], blo[2][4];
#pragma unroll
            for (int mf = 0; mf < 4; mf++) {
                int row = wm + mf * 16 + la7 + arow_off * 8;
                uint32_t off = (uint32_t)(row * 128 + ks * 32 + akseg * 16);
                off ^= (uint32_t)((row & 7) * 16);
                LDMATRIX_X4(ahi[mf][0], ahi[mf][1], ahi[mf][2], ahi[mf][3], base + off);
                LDMATRIX_X4(alo[mf][0], alo[mf][1], alo[mf][2], alo[mf][3], base + 16384 + off);
            }
#pragma unroll
            for (int p = 0; p < 2; p++) {
                int row = wn + p * 16 + la7 + brow_off * 8;
                uint32_t off = (uint32_t)(row * 128 + ks * 32 + bkseg * 16);
                off ^= (uint32_t)((row & 7) * 16);
                LDMATRIX_X4(bhi[p][0], bhi[p][1], bhi[p][2], bhi[p][3], base + 32768 + off);
                LDMATRIX_X4(blo[p][0], blo[p][1], blo[p][2], blo[p][3], base + 49152 + off);
            }
#pragma unroll
            for (int mf = 0; mf < 4; mf++)
#pragma unroll
                for (int nf = 0; nf < 4; nf++) {
                    const int p = nf >> 1, s = (nf & 1) * 2;
                    float* c = acc[mf][nf];
                    MMA_BF16(c[0], c[1], c[2], c[3],
                             ahi[mf][0], ahi[mf][1], ahi[mf][2], ahi[mf][3],
                             bhi[p][s], bhi[p][s + 1]);
                    MMA_BF16(c[0], c[1], c[2], c[3],
                             ahi[mf][0], ahi[mf][1], ahi[mf][2], ahi[mf][3],
                             blo[p][s], blo[p][s + 1]);
                    MMA_BF16(c[0], c[1], c[2], c[3],
                             alo[mf][0], alo[mf][1], alo[mf][2], alo[mf][3],
                             bhi[p][s], bhi[p][s + 1]);
                }
        }
    }

    __syncthreads();
    float* zs = (float*)smp;
    {
        const int cr = lane >> 2, cc = (lane & 3) * 2;
#pragma unroll
        for (int mf = 0; mf < 4; mf++)
#pragma unroll
            for (int nf = 0; nf < 4; nf++) {
                int row = wm + mf * 16 + cr;
                int col = wn + nf * 8 + cc;
                *(float2*)&zs[row * 128 + col]       = make_float2(acc[mf][nf][0], acc[mf][nf][1]);
                *(float2*)&zs[(row + 8) * 128 + col] = make_float2(acc[mf][nf][2], acc[mf][nf][3]);
            }
    }
    __syncthreads();

    const int cseg = tid & 31;
    float4 bv = __ldg((const float4*)(bias + n0 + cseg * 4));
#pragma unroll
    for (int i = 0; i < 16; i++) {
        int r = i * 8 + (tid >> 5);
        float4 v = *(const float4*)&zs[r * 128 + cseg * 4];
        v.x += bv.x; v.y += bv.y; v.z += bv.z; v.w += bv.w;
        *(float4*)(g_zpre + ((size_t)b * kT + r) * kG + n0 + cseg * 4) = v;
    }
}

// ---------------- mma.sync LSTM step: 256 thr, K-chunks of 128 ----------------
// grid (16 nt, 8 mt) = 128 CTAs. CTA tile M=64 x N=128, K=512 in 4 chunks of 128.
// 8 warps as 2(m) x 4(n), warp tile 32x32 (lowest LDSM traffic config).
// smem: 2 stages x 96KB (A hi/lo 16KB each + B hi/lo 32KB each; 256B rows).
#define ST_STG 98304
#define ST_DYN 196608

extern "C" __global__ void __launch_bounds__(256, 1) step_mma_kernel(
    int t,
    const int* __restrict__ seq,
    const float* __restrict__ hprev_f32, int hstride,
    const float* __restrict__ c0,
    float* __restrict__ out)
{
    extern __shared__ __align__(1024) char smp[];
    const uint32_t smb = smem_u32(smp);

    const int tid = threadIdx.x;
    const int wid = tid >> 5, lane = tid & 31;
    const int nt = blockIdx.x, mt = blockIdx.y;
    const int b0 = mt * 64;
    const int n0 = nt * 128;
    const int u0g = nt * 32;

    // ---- epilogue operand prefetch (overlaps GEMM): 8 cells/thread ----
    const int ul = tid & 31;
    float zpf[8][4], cpre[8];
    int seqv[8];
    {
        const float* cin = (t == 0) ? c0 : g_c;
#pragma unroll
        for (int it = 0; it < 8; it++) {
            int r = it * 8 + (tid >> 5);
            int bb = b0 + r;
            const float* zp = g_zpre + ((size_t)bb * kT + t) * kG;
#pragma unroll
            for (int g = 0; g < 4; g++)
                zpf[it][g] = __ldg(zp + g * kUnits + u0g + ul);
            cpre[it] = __ldg(cin + (size_t)bb * kUnits + u0g + ul);
            seqv[it] = __ldg(seq + (size_t)bb * kT + t);
        }
    }

    const __nv_bfloat16* srcA_hi = g_hb_hi[(t + 1) & 1] + (size_t)b0 * kUnits;
    const __nv_bfloat16* srcA_lo = g_hb_lo[(t + 1) & 1] + (size_t)b0 * kUnits;
    const __nv_bfloat16* srcB_hi = g_u_hi + (size_t)n0 * kUnits;
    const __nv_bfloat16* srcB_lo = g_u_lo + (size_t)n0 * kUnits;

    const int wm = (wid & 1) * 32;
    const int wn = (wid >> 1) * 32;

    float acc[2][4][4];
#pragma unroll
    for (int i = 0; i < 2; i++)
#pragma unroll
        for (int j = 0; j < 4; j++)
#pragma unroll
            for (int q = 0; q < 4; q++) acc[i][j][q] = 0.f;

    // one K-chunk = 128 k-elems = 256B per row; 16-byte unit swizzle within 128B halves
    auto issue_chunk = [&](int kc, int stg) {
#pragma unroll
        for (int i = 0; i < 24; i++) {
            int idx = i * 256 + tid;         // 0..6143
            uint32_t dst;
            const __nv_bfloat16* src;
            if (idx < 2048) {                // A: 2 mats x 64 rows x 16 units
                int mat = idx >> 10, un = idx & 1023;
                int r = un >> 4, q = un & 15;
                src = (mat ? srcA_lo : srcA_hi) + (size_t)r * kUnits + kc * 128 + q * 8;
                uint32_t qs = (uint32_t)((q & 8) | ((q ^ r) & 7));
                dst = smb + stg * ST_STG + mat * 16384 + (uint32_t)(r * 256) + qs * 16;
            } else {                         // B: 2 mats x 128 rows x 16 units
                int idxB = idx - 2048;
                int mat = idxB >> 11, un = idxB & 2047;
                int r = un >> 4, q = un & 15;
                src = (mat ? srcB_lo : srcB_hi) + (size_t)r * kUnits + kc * 128 + q * 8;
                uint32_t qs = (uint32_t)((q & 8) | ((q ^ r) & 7));
                dst = smb + stg * ST_STG + 32768 + mat * 32768 + (uint32_t)(r * 256) + qs * 16;
            }
            CP_ASYNC16(dst, src);
        }
        CP_COMMIT();
    };

    issue_chunk(0, 0);

    const int la7 = lane & 7;
    const int arow_off = (lane >> 3) & 1;
    const int akseg   = (lane >> 4) & 1;
    const int brow_off = (lane >> 4) & 1;
    const int bkseg   = (lane >> 3) & 1;

    for (int kc = 0; kc < 4; kc++) {
        CP_WAIT0();
        __syncthreads();
        if (kc < 3) issue_chunk(kc + 1, (kc + 1) & 1);

        const uint32_t base = smb + (kc & 1) * ST_STG;
#pragma unroll
        for (int ks = 0; ks < 8; ks++) {
            uint32_t ahi[2][4], alo[2][4], bhi[2][4], blo[2][4];
#pragma unroll
            for (int mf = 0; mf < 2; mf++) {
                int row = wm + mf * 16 + la7 + arow_off * 8;
                int q = ks * 2 + akseg;
                uint32_t off = (uint32_t)(row * 256 + (((q & 8) | ((q ^ row) & 7)) << 4));
                LDMATRIX_X4(ahi[mf][0], ahi[mf][1], ahi[mf][2], ahi[mf][3], base + off);
                LDMATRIX_X4(alo[mf][0], alo[mf][1], alo[mf][2], alo[mf][3], base + 16384 + off);
            }
#pragma unroll
            for (int p = 0; p < 2; p++) {
                int row = wn + p * 16 + la7 + brow_off * 8;
                int q = ks * 2 + bkseg;
                uint32_t off = (uint32_t)(row * 256 + (((q & 8) | ((q ^ row) & 7)) << 4));
                LDMATRIX_X4(bhi[p][0], bhi[p][1], bhi[p][2], bhi[p][3], base + 32768 + off);
                LDMATRIX_X4(blo[p][0], blo[p][1], blo[p][2], blo[p][3], base + 65536 + off);
            }
#pragma unroll
            for (int mf = 0; mf < 2; mf++)
#pragma unroll
                for (int nf = 0; nf < 4; nf++) {
                    const int p = nf >> 1, s = (nf & 1) * 2;
                    float* c = acc[mf][nf];
                    MMA_BF16(c[0], c[1], c[2], c[3],
                             ahi[mf][0], ahi[mf][1], ahi[mf][2], ahi[mf][3],
                             bhi[p][s], bhi[p][s + 1]);
                    MMA_BF16(c[0], c[1], c[2], c[3],
                             ahi[mf][0], ahi[mf][1], ahi[mf][2], ahi[mf][3],
                             blo[p][s], blo[p][s + 1]);
                    MMA_BF16(c[0], c[1], c[2], c[3],
                             alo[mf][0], alo[mf][1], alo[mf][2], alo[mf][3],
                             bhi[p][s], bhi[p][s + 1]);
                }
        }
    }

    // ---- stage z to smem: 64x128 f32 = 32KB (stage 0 region, idle now) ----
    __syncthreads();
    float* zs = (float*)smp;
    {
        const int cr = lane >> 2, cc = (lane & 3) * 2;
#pragma unroll
        for (int mf = 0; mf < 2; mf++)
#pragma unroll
            for (int nf = 0; nf < 4; nf++) {
                int row = wm + mf * 16 + cr;
                int col = wn + nf * 8 + cc;
                *(float2*)&zs[row * 128 + col]       = make_float2(acc[mf][nf][0], acc[mf][nf][1]);
                *(float2*)&zs[(row + 8) * 128 + col] = make_float2(acc[mf][nf][2], acc[mf][nf][3]);
            }
    }
    __syncthreads();

    // ---- fused LSTM epilogue (+ fused finalize at t = T-1) ----
    __nv_bfloat16* dsthi = g_hb_hi[t & 1];
    __nv_bfloat16* dstlo = g_hb_lo[t & 1];
    const bool lastt = (t == kT - 1);
    float* hfin = out + (size_t)kB * kT * kUnits;
    float* cfin = hfin + (size_t)kB * kUnits;
#pragma unroll
    for (int it = 0; it < 8; it++) {
        int r = it * 8 + (tid >> 5);
        int b = b0 + r;
        int u = u0g + ul;
        float4 z4 = *(const float4*)&zs[r * 128 + ul * 4];
        float zi = z4.x + zpf[it][0];
        float zf = z4.y + zpf[it][1];
        float zg = z4.z + zpf[it][2];
        float zo = z4.w + zpf[it][3];
        float ig = fast_sig(zi);
        float fg = fast_sig(zf);
        float og = fast_sig(zo);
        float cold = cpre[it];
        float cnew = fmaf(fg, cold, ig * fast_tanh(zg));
        float hnew = og * fast_tanh(cnew);
        if (seqv[it] == 0) {
            cnew = cold;
            hnew = __ldg(hprev_f32 + (size_t)b * hstride + u);
        }
        g_c[(size_t)b * kUnits + u] = cnew;
        out[(size_t)b * (kT * kUnits) + (size_t)t * kUnits + u] = hnew;
        __nv_bfloat16 hi, lo;
        split_bf16(hnew, hi, lo);
        dsthi[(size_t)b * kUnits + u] = hi;
        dstlo[(size_t)b * kUnits + u] = lo;
        if (lastt) {
            hfin[(size_t)b * kUnits + u] = hnew;
            cfin[(size_t)b * kUnits + u] = cnew;
        }
    }
}

// ---------------- host ----------------
extern "C" void kernel_launch(void* const* d_in, const int* in_sizes, int n_in,
                              void* d_out, int out_size)
{
    const int*   seq  = (const int*)d_in[0];
    const float* h0   = (const float*)d_in[1];
    const float* c0   = (const float*)d_in[2];
    const float* emb  = (const float*)d_in[3];
    const float* W    = (const float*)d_in[4];
    const float* Umat = (const float*)d_in[5];
    const float* bias = (const float*)d_in[6];
    float* out = (float*)d_out;

    static int configured = 0;
    if (!configured) {
        cudaFuncSetAttribute(precompute_mma_kernel, cudaFuncAttributeMaxDynamicSharedMemorySize, PC_DYN);
        cudaFuncSetAttribute(step_mma_kernel, cudaFuncAttributeMaxDynamicSharedMemorySize, ST_DYN);
        configured = 1;
    }

    const int embBlocks = (kVocab + 7) / 8;
    prep_kernel<<<kG + 8 + kG + embBlocks, 128>>>(Umat, h0, W, emb);

    precompute_mma_kernel<<<dim3(16, kB), 256, PC_DYN>>>(seq, bias);

    for (int t = 0; t < kT; t++) {
        const float* hprev = t ? (out + (size_t)(t - 1) * kUnits) : h0;
        int hstride = t ? (kT * kUnits) : kUnits;
        step_mma_kernel<<<dim3(16, 8), 256, ST_DYN>>>(t, seq, hprev, hstride, c0, out);
    }
}

// round 10
// speedup vs baseline: 1.3628x; 1.2908x over previous
#include <cuda_runtime.h>
#include <cuda_fp16.h>
#include <cstdint>
#include <math.h>

#define kVocab 50000
#define kEmbed 300
#define kEmbP  320
#define kUnits 512
#define kT 128
#define kB 512
#define kG 2048

// ---------------- global scratch ----------------
__device__ float g_zpre[(size_t)kB * kT * kG];
__device__ float g_c[(size_t)kB * kUnits];
__device__ __align__(128) __half g_u[kG * kUnits];               // U^T gate-interleaved, fp16 single
__device__ __align__(128) __half g_hb_hi[2][kB * kUnits];        // h fp16 hi, double buffered
__device__ __align__(128) __half g_hb_lo[2][kB * kUnits];        // h fp16 lo
__device__ __align__(128) __half g_emb_hi[(size_t)kVocab * kEmbP];
__device__ __align__(128) __half g_emb_lo[(size_t)kVocab * kEmbP];
__device__ __align__(128) __half g_wt[kG * kEmbP];               // W^T fp16 single

// ---------------- helpers ----------------
__device__ __forceinline__ uint32_t smem_u32(const void* p) {
    uint32_t a;
    asm("{ .reg .u64 t; cvta.to.shared.u64 t, %1; cvt.u32.u64 %0, t; }" : "=r"(a) : "l"(p));
    return a;
}
#define CP_ASYNC16(dst, src) \
    asm volatile("cp.async.cg.shared.global [%0], [%1], 16;" :: "r"(dst), "l"(src) : "memory")
#define CP_COMMIT() asm volatile("cp.async.commit_group;" ::: "memory")
#define CP_WAIT0()  asm volatile("cp.async.wait_group 0;" ::: "memory")
#define CP_WAIT1()  asm volatile("cp.async.wait_group 1;" ::: "memory")

#define LDMATRIX_X4(r0, r1, r2, r3, addr) \
    asm volatile("ldmatrix.sync.aligned.m8n8.x4.shared.b16 {%0,%1,%2,%3}, [%4];" \
        : "=r"(r0), "=r"(r1), "=r"(r2), "=r"(r3) : "r"(addr))

#define MMA_F16(c0, c1, c2, c3, a0, a1, a2, a3, b0, b1) \
    asm volatile("mma.sync.aligned.m16n8k16.row.col.f32.f16.f16.f32 " \
        "{%0,%1,%2,%3}, {%4,%5,%6,%7}, {%8,%9}, {%0,%1,%2,%3};" \
        : "+f"(c0), "+f"(c1), "+f"(c2), "+f"(c3) \
        : "r"(a0), "r"(a1), "r"(a2), "r"(a3), "r"(b0), "r"(b1))

__device__ __forceinline__ float fast_ex2(float x) { float y; asm("ex2.approx.ftz.f32 %0, %1;" : "=f"(y) : "f"(x)); return y; }
__device__ __forceinline__ float fast_sig(float x) { return __fdividef(1.f, 1.f + fast_ex2(-1.4426950408889634f * x)); }
__device__ __forceinline__ float fast_tanh(float x) {
    float ax = fabsf(x);
    float e = fast_ex2(-2.8853900817779268f * ax);
    float t = __fdividef(1.f - e, 1.f + e);
    return copysignf(t, x);
}
__device__ __forceinline__ void split_f16(float v, __half& hi, __half& lo) {
    hi = __float2half_rn(v);
    lo = __float2half_rn(v - __half2float(hi));
}

// ---------------- prep ----------------
__global__ __launch_bounds__(128) void prep_kernel(const float* __restrict__ U,
                                                   const float* __restrict__ h0,
                                                   const float* __restrict__ W,
                                                   const float* __restrict__ emb) {
    int blk = blockIdx.x;
    if (blk < kG) {                       // U^T gate-interleaved n' = u*4+g, single fp16
        int np = blk;
        int n = (np & 3) * kUnits + (np >> 2);
        for (int k = threadIdx.x; k < kUnits; k += 128)
            g_u[np * kUnits + k] = __float2half_rn(__ldg(U + (size_t)k * kG + n));
    } else if (blk < kG + 8) {            // h0 -> fp16 hi/lo into buffer 1
        int r0 = (blk - kG) * 64;
        for (int i = threadIdx.x; i < 64 * kUnits; i += 128) {
            int r = r0 + (i >> 9), k = i & 511;
            __half hi, lo;
            split_f16(__ldg(h0 + (size_t)r * kUnits + k), hi, lo);
            g_hb_hi[1][r * kUnits + k] = hi;
            g_hb_lo[1][r * kUnits + k] = lo;
        }
    } else if (blk < kG + 8 + kG) {       // W^T row n, padded K, single fp16
        int n = blk - kG - 8;
        for (int k = threadIdx.x; k < kEmbP; k += 128) {
            float v = (k < kEmbed) ? __ldg(W + (size_t)k * kG + n) : 0.f;
            g_wt[n * kEmbP + k] = __float2half_rn(v);
        }
    } else {                              // emb rows, padded, fp16 hi/lo
        int r0 = (blk - kG - 8 - kG) * 8;
        for (int rr = 0; rr < 8; rr++) {
            int row = r0 + rr;
            if (row >= kVocab) break;
            for (int k = threadIdx.x; k < kEmbP; k += 128) {
                float v = (k < kEmbed) ? __ldg(emb + (size_t)row * kEmbed + k) : 0.f;
                __half hi, lo;
                split_f16(v, hi, lo);
                g_emb_hi[(size_t)row * kEmbP + k] = hi;
                g_emb_lo[(size_t)row * kEmbP + k] = lo;
            }
        }
    }
}

// ---------------- precompute Zpre via mma.sync: x(hi+lo fp16) @ W(fp16) ----------------
// grid (16 nt, 512 b), 256 thr. M=128(t) x N=128(n), K=320 in 5 chunks of 64.
// stage: A_hi 16KB + A_lo 16KB + B 16KB = 48KB; 2 stages, 1-deep lookahead.
#define PC_STG 49152
#define PC_DYN 98304

extern "C" __global__ void __launch_bounds__(256, 1) precompute_mma_kernel(
    const int* __restrict__ seq, const float* __restrict__ bias)
{
    extern __shared__ __align__(1024) char smp[];
    const uint32_t smb = smem_u32(smp);
    __shared__ int toks[128];

    const int tid = threadIdx.x;
    const int wid = tid >> 5, lane = tid & 31;
    const int nt = blockIdx.x, b = blockIdx.y;
    const int n0 = nt * 128;

    if (tid < 128) toks[tid] = seq[(size_t)b * kT + tid];
    __syncthreads();

    const int wm = (wid & 1) * 64;
    const int wn = (wid >> 1) * 32;

    float acc[4][4][4];
#pragma unroll
    for (int i = 0; i < 4; i++)
#pragma unroll
        for (int j = 0; j < 4; j++)
#pragma unroll
            for (int q = 0; q < 4; q++) acc[i][j][q] = 0.f;

    auto issue_chunk = [&](int kc, int stg) {
#pragma unroll
        for (int i = 0; i < 12; i++) {
            int idx = i * 256 + tid;       // 0..3071
            uint32_t dst;
            const __half* src;
            if (idx < 2048) {              // A: emb gather, hi/lo
                int mat = idx >> 10, r = (idx >> 3) & 127, q = idx & 7;
                src = (mat ? g_emb_lo : g_emb_hi) + (size_t)toks[r] * kEmbP + kc * 64 + q * 8;
                uint32_t off = (uint32_t)(r * 128 + ((q ^ (r & 7)) * 16));
                dst = smb + stg * PC_STG + mat * 16384 + off;
            } else {                       // B: W^T rows, single
                int idxB = idx - 2048;
                int r = (idxB >> 3) & 127, q = idxB & 7;
                src = g_wt + (size_t)(n0 + r) * kEmbP + kc * 64 + q * 8;
                uint32_t off = (uint32_t)(r * 128 + ((q ^ (r & 7)) * 16));
                dst = smb + stg * PC_STG + 32768 + off;
            }
            CP_ASYNC16(dst, src);
        }
        CP_COMMIT();
    };

    issue_chunk(0, 0);

    const int la7 = lane & 7;
    const int arow_off = (lane >> 3) & 1;
    const int akseg   = (lane >> 4) & 1;
    const int brow_off = (lane >> 4) & 1;
    const int bkseg   = (lane >> 3) & 1;

    for (int kc = 0; kc < 5; kc++) {
        CP_WAIT0();
        __syncthreads();
        if (kc < 4) issue_chunk(kc + 1, (kc + 1) & 1);

        const uint32_t base = smb + (kc & 1) * PC_STG;
#pragma unroll
        for (int ks = 0; ks < 4; ks++) {
            uint32_t ahi[4][4], alo[4][4], bb[2][4];
#pragma unroll
            for (int mf = 0; mf < 4; mf++) {
                int row = wm + mf * 16 + la7 + arow_off * 8;
                uint32_t off = (uint32_t)(row * 128 + ks * 32 + akseg * 16);
                off ^= (uint32_t)((row & 7) * 16);
                LDMATRIX_X4(ahi[mf][0], ahi[mf][1], ahi[mf][2], ahi[mf][3], base + off);
                LDMATRIX_X4(alo[mf][0], alo[mf][1], alo[mf][2], alo[mf][3], base + 16384 + off);
            }
#pragma unroll
            for (int p = 0; p < 2; p++) {
                int row = wn + p * 16 + la7 + brow_off * 8;
                uint32_t off = (uint32_t)(row * 128 + ks * 32 + bkseg * 16);
                off ^= (uint32_t)((row & 7) * 16);
                LDMATRIX_X4(bb[p][0], bb[p][1], bb[p][2], bb[p][3], base + 32768 + off);
            }
#pragma unroll
            for (int mf = 0; mf < 4; mf++)
#pragma unroll
                for (int nf = 0; nf < 4; nf++) {
                    const int p = nf >> 1, s = (nf & 1) * 2;
                    float* c = acc[mf][nf];
                    MMA_F16(c[0], c[1], c[2], c[3],
                            ahi[mf][0], ahi[mf][1], ahi[mf][2], ahi[mf][3],
                            bb[p][s], bb[p][s + 1]);
                    MMA_F16(c[0], c[1], c[2], c[3],
                            alo[mf][0], alo[mf][1], alo[mf][2], alo[mf][3],
                            bb[p][s], bb[p][s + 1]);
                }
        }
    }

    __syncthreads();
    float* zs = (float*)smp;
    {
        const int cr = lane >> 2, cc = (lane & 3) * 2;
#pragma unroll
        for (int mf = 0; mf < 4; mf++)
#pragma unroll
            for (int nf = 0; nf < 4; nf++) {
                int row = wm + mf * 16 + cr;
                int col = wn + nf * 8 + cc;
                *(float2*)&zs[row * 128 + col]       = make_float2(acc[mf][nf][0], acc[mf][nf][1]);
                *(float2*)&zs[(row + 8) * 128 + col] = make_float2(acc[mf][nf][2], acc[mf][nf][3]);
            }
    }
    __syncthreads();

    const int cseg = tid & 31;
    float4 bv = __ldg((const float4*)(bias + n0 + cseg * 4));
#pragma unroll
    for (int i = 0; i < 16; i++) {
        int r = i * 8 + (tid >> 5);
        float4 v = *(const float4*)&zs[r * 128 + cseg * 4];
        v.x += bv.x; v.y += bv.y; v.z += bv.z; v.w += bv.w;
        *(float4*)(g_zpre + ((size_t)b * kT + r) * kG + n0 + cseg * 4) = v;
    }
}

// ---------------- mma.sync LSTM step: (h_hi+h_lo fp16) @ U(fp16) ----------------
// grid (16 nt, 8 mt) = 128 CTAs, 256 thr (8 warps 2x4), warp tile 32x32.
// CTA tile M=64 x N=128, K=512 in 8 chunks of 64.
// stage: A_hi 8KB + A_lo 8KB + B 16KB = 32KB; 3 stages = 96KB.
#define ST_STG 32768
#define ST_DYN 98304

extern "C" __global__ void __launch_bounds__(256, 1) step_mma_kernel(
    int t,
    const int* __restrict__ seq,
    const float* __restrict__ hprev_f32, int hstride,
    const float* __restrict__ c0,
    float* __restrict__ out)
{
    extern __shared__ __align__(1024) char smp[];
    const uint32_t smb = smem_u32(smp);

    const int tid = threadIdx.x;
    const int wid = tid >> 5, lane = tid & 31;
    const int nt = blockIdx.x, mt = blockIdx.y;
    const int b0 = mt * 64;
    const int n0 = nt * 128;
    const int u0g = nt * 32;

    // ---- epilogue operand prefetch (overlaps GEMM) ----
    const int ul = tid & 31;
    float zpf[8][4], cpre[8];
    int seqv[8];
    {
        const float* cin = (t == 0) ? c0 : g_c;
#pragma unroll
        for (int it = 0; it < 8; it++) {
            int r = it * 8 + (tid >> 5);
            int bb = b0 + r;
            const float* zp = g_zpre + ((size_t)bb * kT + t) * kG;
#pragma unroll
            for (int g = 0; g < 4; g++)
                zpf[it][g] = __ldg(zp + g * kUnits + u0g + ul);
            cpre[it] = __ldg(cin + (size_t)bb * kUnits + u0g + ul);
            seqv[it] = __ldg(seq + (size_t)bb * kT + t);
        }
    }

    const __half* srcA_hi = g_hb_hi[(t + 1) & 1] + (size_t)b0 * kUnits;
    const __half* srcA_lo = g_hb_lo[(t + 1) & 1] + (size_t)b0 * kUnits;
    const __half* srcB    = g_u + (size_t)n0 * kUnits;

    const int wm = (wid & 1) * 32;
    const int wn = (wid >> 1) * 32;

    float acc[2][4][4];
#pragma unroll
    for (int i = 0; i < 2; i++)
#pragma unroll
        for (int j = 0; j < 4; j++)
#pragma unroll
            for (int q = 0; q < 4; q++) acc[i][j][q] = 0.f;

    auto issue_chunk = [&](int kc, int stg) {
#pragma unroll
        for (int i = 0; i < 8; i++) {
            int idx = i * 256 + tid;       // 0..2047
            uint32_t dst;
            const __half* src;
            if (idx < 1024) {              // A: h rows (64), hi/lo
                int mat = idx >> 9, r = (idx >> 3) & 63, q = idx & 7;
                src = (mat ? srcA_lo : srcA_hi) + (size_t)r * kUnits + kc * 64 + q * 8;
                uint32_t off = (uint32_t)(r * 128 + ((q ^ (r & 7)) * 16));
                dst = smb + stg * ST_STG + mat * 8192 + off;
            } else {                       // B: U rows (128), single
                int idxB = idx - 1024;
                int r = (idxB >> 3) & 127, q = idxB & 7;
                src = srcB + (size_t)r * kUnits + kc * 64 + q * 8;
                uint32_t off = (uint32_t)(r * 128 + ((q ^ (r & 7)) * 16));
                dst = smb + stg * ST_STG + 16384 + off;
            }
            CP_ASYNC16(dst, src);
        }
        CP_COMMIT();
    };

    issue_chunk(0, 0);
    issue_chunk(1, 1);

    const int la7 = lane & 7;
    const int arow_off = (lane >> 3) & 1;
    const int akseg   = (lane >> 4) & 1;
    const int brow_off = (lane >> 4) & 1;
    const int bkseg   = (lane >> 3) & 1;

    for (int kc = 0; kc < 8; kc++) {
        if (kc < 6) { CP_WAIT1(); } else { CP_WAIT0(); }
        __syncthreads();
        if (kc < 6) issue_chunk(kc + 2, (kc + 2) % 3);

        const uint32_t base = smb + (kc % 3) * ST_STG;
#pragma unroll
        for (int ks = 0; ks < 4; ks++) {
            uint32_t ahi[2][4], alo[2][4], bb[2][4];
#pragma unroll
            for (int mf = 0; mf < 2; mf++) {
                int row = wm + mf * 16 + la7 + arow_off * 8;
                uint32_t off = (uint32_t)(row * 128 + ks * 32 + akseg * 16);
                off ^= (uint32_t)((row & 7) * 16);
                LDMATRIX_X4(ahi[mf][0], ahi[mf][1], ahi[mf][2], ahi[mf][3], base + off);
                LDMATRIX_X4(alo[mf][0], alo[mf][1], alo[mf][2], alo[mf][3], base + 8192 + off);
            }
#pragma unroll
            for (int p = 0; p < 2; p++) {
                int row = wn + p * 16 + la7 + brow_off * 8;
                uint32_t off = (uint32_t)(row * 128 + ks * 32 + bkseg * 16);
                off ^= (uint32_t)((row & 7) * 16);
                LDMATRIX_X4(bb[p][0], bb[p][1], bb[p][2], bb[p][3], base + 16384 + off);
            }
#pragma unroll
            for (int mf = 0; mf < 2; mf++)
#pragma unroll
                for (int nf = 0; nf < 4; nf++) {
                    const int p = nf >> 1, s = (nf & 1) * 2;
                    float* c = acc[mf][nf];
                    MMA_F16(c[0], c[1], c[2], c[3],
                            ahi[mf][0], ahi[mf][1], ahi[mf][2], ahi[mf][3],
                            bb[p][s], bb[p][s + 1]);
                    MMA_F16(c[0], c[1], c[2], c[3],
                            alo[mf][0], alo[mf][1], alo[mf][2], alo[mf][3],
                            bb[p][s], bb[p][s + 1]);
                }
        }
    }

    // ---- stage z to smem: 64x128 f32 = 32KB (stage 0 region) ----
    __syncthreads();
    float* zs = (float*)smp;
    {
        const int cr = lane >> 2, cc = (lane & 3) * 2;
#pragma unroll
        for (int mf = 0; mf < 2; mf++)
#pragma unroll
            for (int nf = 0; nf < 4; nf++) {
                int row = wm + mf * 16 + cr;
                int col = wn + nf * 8 + cc;
                *(float2*)&zs[row * 128 + col]       = make_float2(acc[mf][nf][0], acc[mf][nf][1]);
                *(float2*)&zs[(row + 8) * 128 + col] = make_float2(acc[mf][nf][2], acc[mf][nf][3]);
            }
    }
    __syncthreads();

    // ---- fused LSTM epilogue (+ finalize at t = T-1) ----
    __half* dsthi = g_hb_hi[t & 1];
    __half* dstlo = g_hb_lo[t & 1];
    const bool lastt = (t == kT - 1);
    float* hfin = out + (size_t)kB * kT * kUnits;
    float* cfin = hfin + (size_t)kB * kUnits;
#pragma unroll
    for (int it = 0; it < 8; it++) {
        int r = it * 8 + (tid >> 5);
        int b = b0 + r;
        int u = u0g + ul;
        float4 z4 = *(const float4*)&zs[r * 128 + ul * 4];
        float zi = z4.x + zpf[it][0];
        float zf = z4.y + zpf[it][1];
        float zg = z4.z + zpf[it][2];
        float zo = z4.w + zpf[it][3];
        float ig = fast_sig(zi);
        float fg = fast_sig(zf);
        float og = fast_sig(zo);
        float cold = cpre[it];
        float cnew = fmaf(fg, cold, ig * fast_tanh(zg));
        float hnew = og * fast_tanh(cnew);
        if (seqv[it] == 0) {
            cnew = cold;
            hnew = __ldg(hprev_f32 + (size_t)b * hstride + u);
        }
        g_c[(size_t)b * kUnits + u] = cnew;
        out[(size_t)b * (kT * kUnits) + (size_t)t * kUnits + u] = hnew;
        __half hi, lo;
        split_f16(hnew, hi, lo);
        dsthi[(size_t)b * kUnits + u] = hi;
        dstlo[(size_t)b * kUnits + u] = lo;
        if (lastt) {
            hfin[(size_t)b * kUnits + u] = hnew;
            cfin[(size_t)b * kUnits + u] = cnew;
        }
    }
}

// ---------------- host ----------------
extern "C" void kernel_launch(void* const* d_in, const int* in_sizes, int n_in,
                              void* d_out, int out_size)
{
    const int*   seq  = (const int*)d_in[0];
    const float* h0   = (const float*)d_in[1];
    const float* c0   = (const float*)d_in[2];
    const float* emb  = (const float*)d_in[3];
    const float* W    = (const float*)d_in[4];
    const float* Umat = (const float*)d_in[5];
    const float* bias = (const float*)d_in[6];
    float* out = (float*)d_out;

    static int configured = 0;
    if (!configured) {
        cudaFuncSetAttribute(precompute_mma_kernel, cudaFuncAttributeMaxDynamicSharedMemorySize, PC_DYN);
        cudaFuncSetAttribute(step_mma_kernel, cudaFuncAttributeMaxDynamicSharedMemorySize, ST_DYN);
        configured = 1;
    }

    const int embBlocks = (kVocab + 7) / 8;
    prep_kernel<<<kG + 8 + kG + embBlocks, 128>>>(Umat, h0, W, emb);

    precompute_mma_kernel<<<dim3(16, kB), 256, PC_DYN>>>(seq, bias);

    for (int t = 0; t < kT; t++) {
        const float* hprev = t ? (out + (size_t)(t - 1) * kUnits) : h0;
        int hstride = t ? (kT * kUnits) : kUnits;
        step_mma_kernel<<<dim3(16, 8), 256, ST_DYN>>>(t, seq, hprev, hstride, c0, out);
    }
}

// round 11
// speedup vs baseline: 1.7160x; 1.2591x over previous
#include <cuda_runtime.h>
#include <cuda_fp16.h>
#include <cstdint>
#include <math.h>

#define kVocab 50000
#define kEmbed 300
#define kEmbP  320
#define kUnits 512
#define kT 128
#define kB 512
#define kG 2048

// ---------------- global scratch ----------------
__device__ float g_zpre[(size_t)kB * kT * kG];
__device__ float g_c[(size_t)kB * kUnits];
__device__ __align__(128) __half g_u[kG * kUnits];               // U^T gate-interleaved, fp16
__device__ __align__(128) __half g_hb[2][kB * kUnits];           // h fp16 single, double buffered
__device__ __align__(128) __half g_emb_hi[(size_t)kVocab * kEmbP];
__device__ __align__(128) __half g_emb_lo[(size_t)kVocab * kEmbP];
__device__ __align__(128) __half g_wt[kG * kEmbP];               // W^T fp16

// ---------------- helpers ----------------
__device__ __forceinline__ uint32_t smem_u32(const void* p) {
    uint32_t a;
    asm("{ .reg .u64 t; cvta.to.shared.u64 t, %1; cvt.u32.u64 %0, t; }" : "=r"(a) : "l"(p));
    return a;
}
#define CP_ASYNC16(dst, src) \
    asm volatile("cp.async.cg.shared.global [%0], [%1], 16;" :: "r"(dst), "l"(src) : "memory")
#define CP_COMMIT() asm volatile("cp.async.commit_group;" ::: "memory")
#define CP_WAIT0()  asm volatile("cp.async.wait_group 0;" ::: "memory")
#define CP_WAIT1()  asm volatile("cp.async.wait_group 1;" ::: "memory")

#define LDMATRIX_X4(r0, r1, r2, r3, addr) \
    asm volatile("ldmatrix.sync.aligned.m8n8.x4.shared.b16 {%0,%1,%2,%3}, [%4];" \
        : "=r"(r0), "=r"(r1), "=r"(r2), "=r"(r3) : "r"(addr))

#define MMA_F16(c0, c1, c2, c3, a0, a1, a2, a3, b0, b1) \
    asm volatile("mma.sync.aligned.m16n8k16.row.col.f32.f16.f16.f32 " \
        "{%0,%1,%2,%3}, {%4,%5,%6,%7}, {%8,%9}, {%0,%1,%2,%3};" \
        : "+f"(c0), "+f"(c1), "+f"(c2), "+f"(c3) \
        : "r"(a0), "r"(a1), "r"(a2), "r"(a3), "r"(b0), "r"(b1))

__device__ __forceinline__ float fast_ex2(float x) { float y; asm("ex2.approx.ftz.f32 %0, %1;" : "=f"(y) : "f"(x)); return y; }
__device__ __forceinline__ float fast_sig(float x) { return __fdividef(1.f, 1.f + fast_ex2(-1.4426950408889634f * x)); }
__device__ __forceinline__ float fast_tanh(float x) {
    float ax = fabsf(x);
    float e = fast_ex2(-2.8853900817779268f * ax);
    float t = __fdividef(1.f - e, 1.f + e);
    return copysignf(t, x);
}
__device__ __forceinline__ void split_f16(float v, __half& hi, __half& lo) {
    hi = __float2half_rn(v);
    lo = __float2half_rn(v - __half2float(hi));
}

// ---------------- prep ----------------
__global__ __launch_bounds__(128) void prep_kernel(const float* __restrict__ U,
                                                   const float* __restrict__ h0,
                                                   const float* __restrict__ W,
                                                   const float* __restrict__ emb) {
    int blk = blockIdx.x;
    if (blk < kG) {                       // U^T gate-interleaved n' = u*4+g, fp16
        int np = blk;
        int n = (np & 3) * kUnits + (np >> 2);
        for (int k = threadIdx.x; k < kUnits; k += 128)
            g_u[np * kUnits + k] = __float2half_rn(__ldg(U + (size_t)k * kG + n));
    } else if (blk < kG + 8) {            // h0 -> fp16 into buffer 1
        int r0 = (blk - kG) * 64;
        for (int i = threadIdx.x; i < 64 * kUnits; i += 128) {
            int r = r0 + (i >> 9), k = i & 511;
            g_hb[1][r * kUnits + k] = __float2half_rn(__ldg(h0 + (size_t)r * kUnits + k));
        }
    } else if (blk < kG + 8 + kG) {       // W^T row n, padded K, fp16
        int n = blk - kG - 8;
        for (int k = threadIdx.x; k < kEmbP; k += 128) {
            float v = (k < kEmbed) ? __ldg(W + (size_t)k * kG + n) : 0.f;
            g_wt[n * kEmbP + k] = __float2half_rn(v);
        }
    } else {                              // emb rows, padded, fp16 hi/lo
        int r0 = (blk - kG - 8 - kG) * 8;
        for (int rr = 0; rr < 8; rr++) {
            int row = r0 + rr;
            if (row >= kVocab) break;
            for (int k = threadIdx.x; k < kEmbP; k += 128) {
                float v = (k < kEmbed) ? __ldg(emb + (size_t)row * kEmbed + k) : 0.f;
                __half hi, lo;
                split_f16(v, hi, lo);
                g_emb_hi[(size_t)row * kEmbP + k] = hi;
                g_emb_lo[(size_t)row * kEmbP + k] = lo;
            }
        }
    }
}

// ---------------- precompute Zpre via mma.sync: x(hi+lo fp16) @ W(fp16) ----------------
// (unchanged from R10 pass)
#define PC_STG 49152
#define PC_DYN 98304

extern "C" __global__ void __launch_bounds__(256, 1) precompute_mma_kernel(
    const int* __restrict__ seq, const float* __restrict__ bias)
{
    extern __shared__ __align__(1024) char smp[];
    const uint32_t smb = smem_u32(smp);
    __shared__ int toks[128];

    const int tid = threadIdx.x;
    const int wid = tid >> 5, lane = tid & 31;
    const int nt = blockIdx.x, b = blockIdx.y;
    const int n0 = nt * 128;

    if (tid < 128) toks[tid] = seq[(size_t)b * kT + tid];
    __syncthreads();

    const int wm = (wid & 1) * 64;
    const int wn = (wid >> 1) * 32;

    float acc[4][4][4];
#pragma unroll
    for (int i = 0; i < 4; i++)
#pragma unroll
        for (int j = 0; j < 4; j++)
#pragma unroll
            for (int q = 0; q < 4; q++) acc[i][j][q] = 0.f;

    auto issue_chunk = [&](int kc, int stg) {
#pragma unroll
        for (int i = 0; i < 12; i++) {
            int idx = i * 256 + tid;
            uint32_t dst;
            const __half* src;
            if (idx < 2048) {
                int mat = idx >> 10, r = (idx >> 3) & 127, q = idx & 7;
                src = (mat ? g_emb_lo : g_emb_hi) + (size_t)toks[r] * kEmbP + kc * 64 + q * 8;
                uint32_t off = (uint32_t)(r * 128 + ((q ^ (r & 7)) * 16));
                dst = smb + stg * PC_STG + mat * 16384 + off;
            } else {
                int idxB = idx - 2048;
                int r = (idxB >> 3) & 127, q = idxB & 7;
                src = g_wt + (size_t)(n0 + r) * kEmbP + kc * 64 + q * 8;
                uint32_t off = (uint32_t)(r * 128 + ((q ^ (r & 7)) * 16));
                dst = smb + stg * PC_STG + 32768 + off;
            }
            CP_ASYNC16(dst, src);
        }
        CP_COMMIT();
    };

    issue_chunk(0, 0);

    const int la7 = lane & 7;
    const int arow_off = (lane >> 3) & 1;
    const int akseg   = (lane >> 4) & 1;
    const int brow_off = (lane >> 4) & 1;
    const int bkseg   = (lane >> 3) & 1;

    for (int kc = 0; kc < 5; kc++) {
        CP_WAIT0();
        __syncthreads();
        if (kc < 4) issue_chunk(kc + 1, (kc + 1) & 1);

        const uint32_t base = smb + (kc & 1) * PC_STG;
#pragma unroll
        for (int ks = 0; ks < 4; ks++) {
            uint32_t ahi[4][4], alo[4][4], bb[2][4];
#pragma unroll
            for (int mf = 0; mf < 4; mf++) {
                int row = wm + mf * 16 + la7 + arow_off * 8;
                uint32_t off = (uint32_t)(row * 128 + ks * 32 + akseg * 16);
                off ^= (uint32_t)((row & 7) * 16);
                LDMATRIX_X4(ahi[mf][0], ahi[mf][1], ahi[mf][2], ahi[mf][3], base + off);
                LDMATRIX_X4(alo[mf][0], alo[mf][1], alo[mf][2], alo[mf][3], base + 16384 + off);
            }
#pragma unroll
            for (int p = 0; p < 2; p++) {
                int row = wn + p * 16 + la7 + brow_off * 8;
                uint32_t off = (uint32_t)(row * 128 + ks * 32 + bkseg * 16);
                off ^= (uint32_t)((row & 7) * 16);
                LDMATRIX_X4(bb[p][0], bb[p][1], bb[p][2], bb[p][3], base + 32768 + off);
            }
#pragma unroll
            for (int mf = 0; mf < 4; mf++)
#pragma unroll
                for (int nf = 0; nf < 4; nf++) {
                    const int p = nf >> 1, s = (nf & 1) * 2;
                    float* c = acc[mf][nf];
                    MMA_F16(c[0], c[1], c[2], c[3],
                            ahi[mf][0], ahi[mf][1], ahi[mf][2], ahi[mf][3],
                            bb[p][s], bb[p][s + 1]);
                    MMA_F16(c[0], c[1], c[2], c[3],
                            alo[mf][0], alo[mf][1], alo[mf][2], alo[mf][3],
                            bb[p][s], bb[p][s + 1]);
                }
        }
    }

    __syncthreads();
    float* zs = (float*)smp;
    {
        const int cr = lane >> 2, cc = (lane & 3) * 2;
#pragma unroll
        for (int mf = 0; mf < 4; mf++)
#pragma unroll
            for (int nf = 0; nf < 4; nf++) {
                int row = wm + mf * 16 + cr;
                int col = wn + nf * 8 + cc;
                *(float2*)&zs[row * 128 + col]       = make_float2(acc[mf][nf][0], acc[mf][nf][1]);
                *(float2*)&zs[(row + 8) * 128 + col] = make_float2(acc[mf][nf][2], acc[mf][nf][3]);
            }
    }
    __syncthreads();

    const int cseg = tid & 31;
    float4 bv = __ldg((const float4*)(bias + n0 + cseg * 4));
#pragma unroll
    for (int i = 0; i < 16; i++) {
        int r = i * 8 + (tid >> 5);
        float4 v = *(const float4*)&zs[r * 128 + cseg * 4];
        v.x += bv.x; v.y += bv.y; v.z += bv.z; v.w += bv.w;
        *(float4*)(g_zpre + ((size_t)b * kT + r) * kG + n0 + cseg * 4) = v;
    }
}

// ---------------- mma.sync LSTM step: h(fp16) @ U(fp16), single pass ----------------
// grid (16 nt, 8 mt) = 128 CTAs, 256 thr (8 warps 2x4), warp tile 32x32.
// CTA tile M=64 x N=128, K=512 in 8 chunks of 64.
// stage: A 8KB + B 16KB = 24KB; 3 stages = 72KB.
#define ST_STG 24576
#define ST_DYN 73728

extern "C" __global__ void __launch_bounds__(256, 1) step_mma_kernel(
    int t,
    const int* __restrict__ seq,
    const float* __restrict__ hprev_f32, int hstride,
    const float* __restrict__ c0,
    float* __restrict__ out)
{
    extern __shared__ __align__(1024) char smp[];
    const uint32_t smb = smem_u32(smp);

    const int tid = threadIdx.x;
    const int wid = tid >> 5, lane = tid & 31;
    const int nt = blockIdx.x, mt = blockIdx.y;
    const int b0 = mt * 64;
    const int n0 = nt * 128;
    const int u0g = nt * 32;

    // ---- epilogue operand prefetch (overlaps GEMM) ----
    const int ul = tid & 31;
    float zpf[8][4], cpre[8];
    int seqv[8];
    {
        const float* cin = (t == 0) ? c0 : g_c;
#pragma unroll
        for (int it = 0; it < 8; it++) {
            int r = it * 8 + (tid >> 5);
            int bb = b0 + r;
            const float* zp = g_zpre + ((size_t)bb * kT + t) * kG;
#pragma unroll
            for (int g = 0; g < 4; g++)
                zpf[it][g] = __ldg(zp + g * kUnits + u0g + ul);
            cpre[it] = __ldg(cin + (size_t)bb * kUnits + u0g + ul);
            seqv[it] = __ldg(seq + (size_t)bb * kT + t);
        }
    }

    const __half* srcA = g_hb[(t + 1) & 1] + (size_t)b0 * kUnits;
    const __half* srcB = g_u + (size_t)n0 * kUnits;

    const int wm = (wid & 1) * 32;
    const int wn = (wid >> 1) * 32;

    float acc[2][4][4];
#pragma unroll
    for (int i = 0; i < 2; i++)
#pragma unroll
        for (int j = 0; j < 4; j++)
#pragma unroll
            for (int q = 0; q < 4; q++) acc[i][j][q] = 0.f;

    auto issue_chunk = [&](int kc, int stg) {
#pragma unroll
        for (int i = 0; i < 6; i++) {
            int idx = i * 256 + tid;       // 0..1535
            uint32_t dst;
            const __half* src;
            if (idx < 512) {               // A: h rows (64), single
                int r = idx >> 3, q = idx & 7;
                src = srcA + (size_t)r * kUnits + kc * 64 + q * 8;
                uint32_t off = (uint32_t)(r * 128 + ((q ^ (r & 7)) * 16));
                dst = smb + stg * ST_STG + off;
            } else {                       // B: U rows (128), single
                int idxB = idx - 512;
                int r = idxB >> 3, q = idxB & 7;
                src = srcB + (size_t)r * kUnits + kc * 64 + q * 8;
                uint32_t off = (uint32_t)(r * 128 + ((q ^ (r & 7)) * 16));
                dst = smb + stg * ST_STG + 8192 + off;
            }
            CP_ASYNC16(dst, src);
        }
        CP_COMMIT();
    };

    issue_chunk(0, 0);
    issue_chunk(1, 1);

    const int la7 = lane & 7;
    const int arow_off = (lane >> 3) & 1;
    const int akseg   = (lane >> 4) & 1;
    const int brow_off = (lane >> 4) & 1;
    const int bkseg   = (lane >> 3) & 1;

    for (int kc = 0; kc < 8; kc++) {
        if (kc < 6) { CP_WAIT1(); } else { CP_WAIT0(); }
        __syncthreads();
        if (kc < 6) issue_chunk(kc + 2, (kc + 2) % 3);

        const uint32_t base = smb + (kc % 3) * ST_STG;
#pragma unroll
        for (int ks = 0; ks < 4; ks++) {
            uint32_t aa[2][4], bb[2][4];
#pragma unroll
            for (int mf = 0; mf < 2; mf++) {
                int row = wm + mf * 16 + la7 + arow_off * 8;
                uint32_t off = (uint32_t)(row * 128 + ks * 32 + akseg * 16);
                off ^= (uint32_t)((row & 7) * 16);
                LDMATRIX_X4(aa[mf][0], aa[mf][1], aa[mf][2], aa[mf][3], base + off);
            }
#pragma unroll
            for (int p = 0; p < 2; p++) {
                int row = wn + p * 16 + la7 + brow_off * 8;
                uint32_t off = (uint32_t)(row * 128 + ks * 32 + bkseg * 16);
                off ^= (uint32_t)((row & 7) * 16);
                LDMATRIX_X4(bb[p][0], bb[p][1], bb[p][2], bb[p][3], base + 8192 + off);
            }
#pragma unroll
            for (int mf = 0; mf < 2; mf++)
#pragma unroll
                for (int nf = 0; nf < 4; nf++) {
                    const int p = nf >> 1, s = (nf & 1) * 2;
                    float* c = acc[mf][nf];
                    MMA_F16(c[0], c[1], c[2], c[3],
                            aa[mf][0], aa[mf][1], aa[mf][2], aa[mf][3],
                            bb[p][s], bb[p][s + 1]);
                }
        }
    }

    // ---- stage z to smem: 64x128 f32 = 32KB (stages 0-1 region) ----
    __syncthreads();
    float* zs = (float*)smp;
    {
        const int cr = lane >> 2, cc = (lane & 3) * 2;
#pragma unroll
        for (int mf = 0; mf < 2; mf++)
#pragma unroll
            for (int nf = 0; nf < 4; nf++) {
                int row = wm + mf * 16 + cr;
                int col = wn + nf * 8 + cc;
                *(float2*)&zs[row * 128 + col]       = make_float2(acc[mf][nf][0], acc[mf][nf][1]);
                *(float2*)&zs[(row + 8) * 128 + col] = make_float2(acc[mf][nf][2], acc[mf][nf][3]);
            }
    }
    __syncthreads();

    // ---- fused LSTM epilogue (+ finalize at t = T-1) ----
    __half* dsth = g_hb[t & 1];
    const bool lastt = (t == kT - 1);
    float* hfin = out + (size_t)kB * kT * kUnits;
    float* cfin = hfin + (size_t)kB * kUnits;
#pragma unroll
    for (int it = 0; it < 8; it++) {
        int r = it * 8 + (tid >> 5);
        int b = b0 + r;
        int u = u0g + ul;
        float4 z4 = *(const float4*)&zs[r * 128 + ul * 4];
        float zi = z4.x + zpf[it][0];
        float zf = z4.y + zpf[it][1];
        float zg = z4.z + zpf[it][2];
        float zo = z4.w + zpf[it][3];
        float ig = fast_sig(zi);
        float fg = fast_sig(zf);
        float og = fast_sig(zo);
        float cold = cpre[it];
        float cnew = fmaf(fg, cold, ig * fast_tanh(zg));
        float hnew = og * fast_tanh(cnew);
        if (seqv[it] == 0) {
            cnew = cold;
            hnew = __ldg(hprev_f32 + (size_t)b * hstride + u);
        }
        g_c[(size_t)b * kUnits + u] = cnew;
        out[(size_t)b * (kT * kUnits) + (size_t)t * kUnits + u] = hnew;
        dsth[(size_t)b * kUnits + u] = __float2half_rn(hnew);
        if (lastt) {
            hfin[(size_t)b * kUnits + u] = hnew;
            cfin[(size_t)b * kUnits + u] = cnew;
        }
    }
}

// ---------------- host ----------------
extern "C" void kernel_launch(void* const* d_in, const int* in_sizes, int n_in,
                              void* d_out, int out_size)
{
    const int*   seq  = (const int*)d_in[0];
    const float* h0   = (const float*)d_in[1];
    const float* c0   = (const float*)d_in[2];
    const float* emb  = (const float*)d_in[3];
    const float* W    = (const float*)d_in[4];
    const float* Umat = (const float*)d_in[5];
    const float* bias = (const float*)d_in[6];
    float* out = (float*)d_out;

    static int configured = 0;
    if (!configured) {
        cudaFuncSetAttribute(precompute_mma_kernel, cudaFuncAttributeMaxDynamicSharedMemorySize, PC_DYN);
        cudaFuncSetAttribute(step_mma_kernel, cudaFuncAttributeMaxDynamicSharedMemorySize, ST_DYN);
        configured = 1;
    }

    const int embBlocks = (kVocab + 7) / 8;
    prep_kernel<<<kG + 8 + kG + embBlocks, 128>>>(Umat, h0, W, emb);

    precompute_mma_kernel<<<dim3(16, kB), 256, PC_DYN>>>(seq, bias);

    for (int t = 0; t < kT; t++) {
        const float* hprev = t ? (out + (size_t)(t - 1) * kUnits) : h0;
        int hstride = t ? (kT * kUnits) : kUnits;
        step_mma_kernel<<<dim3(16, 8), 256, ST_DYN>>>(t, seq, hprev, hstride, c0, out);
    }
}